// round 1
// baseline (speedup 1.0000x reference)
#include <cuda_runtime.h>
#include <math.h>

// ---------------------------------------------------------------------------
// DeepSeek V2 MLA attention prefill, fp32 correctness-first implementation.
// T=2048, H=32, HIDDEN=5120, Q_LORA=1536, KV_LORA=512, D_QK=192, D_V=128.
// ---------------------------------------------------------------------------

namespace {
constexpr int T_      = 2048;
constexpr int H_      = 32;
constexpr int HIDDEN_ = 5120;
constexpr int QL_     = 1536;
constexpr int KVL_    = 512;
constexpr int DN_     = 128;   // d_nope
constexpr int DR_     = 64;    // d_rope
constexpr int DQK_    = 192;
constexpr int DV_     = 128;
constexpr float EPS_  = 1e-6f;
}

// ------------------------- scratch (static device) -------------------------
__device__ float g_qa[(long)T_ * QL_];                 // 12.6 MB
__device__ float g_q [(long)T_ * H_ * DQK_];           // 50.3 MB
__device__ float g_ckv[(long)T_ * (KVL_ + DR_)];       // 4.7 MB
__device__ float g_cn [(long)T_ * KVL_];               // 4.2 MB
__device__ float g_kv [(long)T_ * H_ * (DN_ + DV_)];   // 67 MB
__device__ float g_kr [(long)T_ * DR_];                // 0.5 MB
__device__ float g_k  [(long)T_ * H_ * DQK_];          // 50.3 MB
__device__ float g_scores[(long)H_ * T_ * T_];         // 537 MB
__device__ float g_ctx[(long)T_ * H_ * DV_];           // 33.6 MB

// ------------------------------- SGEMM -------------------------------------
// C[M,N] = alpha * A @ B     (NT=false: B is K x N row-major)
//                            (NT=true : B is N x K row-major, C = A @ B^T)
// CAUSAL: 0 = none; 1 = skip tiles strictly above the diagonal (scores);
//         2 = clamp K to (by+1)*BM (PV with zeroed upper-tri probs).
template<bool NT, int CAUSAL>
__global__ void sgemm_kernel(const float* __restrict__ A,
                             const float* __restrict__ B,
                             float* __restrict__ C,
                             int M, int N, int K,
                             int lda, int ldb, int ldc,
                             long sA, long sB, long sC,
                             float alpha)
{
    constexpr int BM = 128, BN = 128, BK = 8, TM = 8, TN = 8;
    const int bx = blockIdx.x, by = blockIdx.y, bz = blockIdx.z;
    if (CAUSAL == 1 && bx > by) return;

    int Keff = K;
    if (CAUSAL == 2) { int lim = (by + 1) * BM; if (lim < Keff) Keff = lim; }

    A += (long)bz * sA;
    B += (long)bz * sB;
    C += (long)bz * sC;

    __shared__ __align__(16) float As[BK][BM];
    __shared__ __align__(16) float Bs[BK][BN];

    const int tid = threadIdx.x;
    const int tx = tid & 15, ty = tid >> 4;
    const int rowBase = by * BM, colBase = bx * BN;

    float acc[TM][TN] = {};

    for (int k0 = 0; k0 < Keff; k0 += BK) {
        // ---- load A tile (M rows always in range: M % 128 == 0, K % 8 == 0)
        #pragma unroll
        for (int e = tid; e < BM * BK; e += 256) {
            int r = e >> 3, c = e & 7;
            As[c][r] = A[(long)(rowBase + r) * lda + (k0 + c)];
        }
        // ---- load B tile
        if (NT) {
            #pragma unroll
            for (int e = tid; e < BN * BK; e += 256) {
                int jr = e >> 3, kc = e & 7;
                int gj = colBase + jr;
                Bs[kc][jr] = (gj < N) ? B[(long)gj * ldb + (k0 + kc)] : 0.0f;
            }
        } else {
            #pragma unroll
            for (int e = tid; e < BK * BN; e += 256) {
                int r = e >> 7, c = e & 127;
                int gc = colBase + c;
                Bs[r][c] = (gc < N) ? B[(long)(k0 + r) * ldb + gc] : 0.0f;
            }
        }
        __syncthreads();

        #pragma unroll
        for (int kk = 0; kk < BK; kk++) {
            const float4* ap = reinterpret_cast<const float4*>(&As[kk][ty * TM]);
            const float4* bp = reinterpret_cast<const float4*>(&Bs[kk][tx * TN]);
            float4 a0 = ap[0], a1 = ap[1];
            float4 b0 = bp[0], b1 = bp[1];
            float ra[TM] = {a0.x, a0.y, a0.z, a0.w, a1.x, a1.y, a1.z, a1.w};
            float rb[TN] = {b0.x, b0.y, b0.z, b0.w, b1.x, b1.y, b1.z, b1.w};
            #pragma unroll
            for (int m = 0; m < TM; m++)
                #pragma unroll
                for (int n = 0; n < TN; n++)
                    acc[m][n] += ra[m] * rb[n];
        }
        __syncthreads();
    }

    #pragma unroll
    for (int m = 0; m < TM; m++) {
        int gr = rowBase + ty * TM + m;
        #pragma unroll
        for (int n = 0; n < TN; n++) {
            int gc = colBase + tx * TN + n;
            if (gc < N) C[(long)gr * ldc + gc] = alpha * acc[m][n];
        }
    }
}

// ------------------------------ RMSNorm ------------------------------------
__global__ void rmsnorm_kernel(const float* __restrict__ x,
                               const float* __restrict__ w,
                               float* __restrict__ y,
                               int L, int ldx, int ldy)
{
    const int row = blockIdx.x, tid = threadIdx.x;
    const float* xr = x + (long)row * ldx;
    float* yr = y + (long)row * ldy;

    __shared__ float red[256];
    float s = 0.0f;
    for (int i = tid; i < L; i += 256) { float v = xr[i]; s += v * v; }
    red[tid] = s; __syncthreads();
    for (int o = 128; o > 0; o >>= 1) {
        if (tid < o) red[tid] += red[tid + o];
        __syncthreads();
    }
    const float scale = rsqrtf(red[0] / (float)L + EPS_);
    for (int i = tid; i < L; i += 256) yr[i] = xr[i] * scale * w[i];
}

// -------------------------------- RoPE -------------------------------------
// deinterleave (even|odd halves) then y*cos + rotate_half(y)*sin, 64 lanes.
__global__ void rope_kernel(const float* __restrict__ x, float* __restrict__ o,
                            const float* __restrict__ cosT,
                            const float* __restrict__ sinT,
                            long sxt, int sxh, long sot, int soh)
{
    const int h = blockIdx.x, t = blockIdx.y, i = threadIdx.x;  // i < 64
    const float* xp = x + (long)t * sxt + (long)h * sxh;
    float* op = o + (long)t * sot + (long)h * soh;

    __shared__ float xs[64];
    __shared__ float ys[64];
    xs[i] = xp[i];
    __syncthreads();
    float y = (i < 32) ? xs[2 * i] : xs[2 * (i - 32) + 1];
    ys[i] = y;
    __syncthreads();
    float rot = (i < 32) ? -ys[i + 32] : ys[i - 32];
    op[i] = y * cosT[(long)t * DR_ + i] + rot * sinT[(long)t * DR_ + i];
}

// ------------------------------ build K ------------------------------------
// k[t,h,0:128] = kv[t,h,0:128];  k[t,h,128:192] = kr[t,:] (broadcast over h)
__global__ void build_k_kernel(const float* __restrict__ kv,
                               const float* __restrict__ kr,
                               float* __restrict__ k)
{
    const int h = blockIdx.x, t = blockIdx.y, i = threadIdx.x;  // i < 192
    float v;
    if (i < DN_) v = kv[(long)t * (H_ * (DN_ + DV_)) + h * (DN_ + DV_) + i];
    else         v = kr[(long)t * DR_ + (i - DN_)];
    k[(long)t * (H_ * DQK_) + h * DQK_ + i] = v;
}

// --------------------------- causal softmax --------------------------------
__global__ void softmax_kernel(float* __restrict__ S)
{
    const int i = blockIdx.x, h = blockIdx.y, tid = threadIdx.x;
    float* row = S + ((long)h * T_ + i) * T_;
    const int len = i + 1;

    __shared__ float red[256];

    float m = -3.4e38f;
    for (int j = tid; j < len; j += 256) m = fmaxf(m, row[j]);
    red[tid] = m; __syncthreads();
    for (int o = 128; o > 0; o >>= 1) {
        if (tid < o) red[tid] = fmaxf(red[tid], red[tid + o]);
        __syncthreads();
    }
    m = red[0]; __syncthreads();

    float sum = 0.0f;
    for (int j = tid; j < len; j += 256) {
        float e = expf(row[j] - m);
        row[j] = e;
        sum += e;
    }
    red[tid] = sum; __syncthreads();
    for (int o = 128; o > 0; o >>= 1) {
        if (tid < o) red[tid] += red[tid + o];
        __syncthreads();
    }
    const float inv = 1.0f / red[0];

    for (int j = tid; j < len; j += 256) row[j] *= inv;
    for (int j = len + tid; j < T_; j += 256) row[j] = 0.0f;  // needed by PV
}

// ------------------------------- launch ------------------------------------
extern "C" void kernel_launch(void* const* d_in, const int* in_sizes, int n_in,
                              void* d_out, int out_size)
{
    const float* hidden = (const float*)d_in[0];
    const float* cosT   = (const float*)d_in[1];
    const float* sinT   = (const float*)d_in[2];
    const float* wq_a   = (const float*)d_in[3];
    const float* q_ln   = (const float*)d_in[4];
    const float* wq_b   = (const float*)d_in[5];
    const float* wkv_a  = (const float*)d_in[6];
    const float* kv_ln  = (const float*)d_in[7];
    const float* wkv_b  = (const float*)d_in[8];
    const float* wo     = (const float*)d_in[9];
    float* out = (float*)d_out;

    static float *qa = nullptr, *q = nullptr, *ckv = nullptr, *cn = nullptr,
                 *kv = nullptr, *kr = nullptr, *k = nullptr, *sc = nullptr,
                 *ctx = nullptr;
    if (!qa) {
        cudaGetSymbolAddress((void**)&qa,  g_qa);
        cudaGetSymbolAddress((void**)&q,   g_q);
        cudaGetSymbolAddress((void**)&ckv, g_ckv);
        cudaGetSymbolAddress((void**)&cn,  g_cn);
        cudaGetSymbolAddress((void**)&kv,  g_kv);
        cudaGetSymbolAddress((void**)&kr,  g_kr);
        cudaGetSymbolAddress((void**)&k,   g_k);
        cudaGetSymbolAddress((void**)&sc,  g_scores);
        cudaGetSymbolAddress((void**)&ctx, g_ctx);
    }

    const float scaling = 0.07216878364870323f;  // 192^-0.5
    const dim3 blk(256);

    // 1) q_a = hidden @ wq_a                       [2048 x 1536]
    sgemm_kernel<false, 0><<<dim3(12, 16, 1), blk>>>(
        hidden, wq_a, qa, T_, QL_, HIDDEN_, HIDDEN_, QL_, QL_, 0, 0, 0, 1.0f);

    // 2) rmsnorm(q_a) in place
    rmsnorm_kernel<<<T_, 256>>>(qa, q_ln, qa, QL_, QL_, QL_);

    // 3) q = q_a_n @ wq_b                          [2048 x 6144]
    sgemm_kernel<false, 0><<<dim3(48, 16, 1), blk>>>(
        qa, wq_b, q, T_, H_ * DQK_, QL_, QL_, H_ * DQK_, H_ * DQK_, 0, 0, 0, 1.0f);

    // 4) ckv = hidden @ wkv_a                      [2048 x 576]
    sgemm_kernel<false, 0><<<dim3(5, 16, 1), blk>>>(
        hidden, wkv_a, ckv, T_, KVL_ + DR_, HIDDEN_,
        HIDDEN_, KVL_ + DR_, KVL_ + DR_, 0, 0, 0, 1.0f);

    // 5) cn = rmsnorm(ckv[:, :512])
    rmsnorm_kernel<<<T_, 256>>>(ckv, kv_ln, cn, KVL_, KVL_ + DR_, KVL_);

    // 6) kv = cn @ wkv_b                           [2048 x 8192]
    sgemm_kernel<false, 0><<<dim3(64, 16, 1), blk>>>(
        cn, wkv_b, kv, T_, H_ * (DN_ + DV_), KVL_,
        KVL_, H_ * (DN_ + DV_), H_ * (DN_ + DV_), 0, 0, 0, 1.0f);

    // 7) RoPE on q_pe (in place), per (h, t)
    rope_kernel<<<dim3(H_, T_), 64>>>(q + DN_, q + DN_, cosT, sinT,
                                      H_ * DQK_, DQK_, H_ * DQK_, DQK_);

    // 8) RoPE on k_pe -> kr
    rope_kernel<<<dim3(1, T_), 64>>>(ckv + KVL_, kr, cosT, sinT,
                                     KVL_ + DR_, 0, DR_, 0);

    // 9) assemble K = [k_nope | broadcast k_rope]  [2048 x 32 x 192]
    build_k_kernel<<<dim3(H_, T_), 192>>>(kv, kr, k);

    // 10) scores[h] = scaling * q_h @ k_h^T (causal tile skip)  [32 x 2048 x 2048]
    sgemm_kernel<true, 1><<<dim3(16, 16, H_), blk>>>(
        q, k, sc, T_, T_, DQK_,
        H_ * DQK_, H_ * DQK_, T_,
        DQK_, DQK_, (long)T_ * T_, scaling);

    // 11) causal softmax rows (zeros above diagonal)
    softmax_kernel<<<dim3(T_, H_), 256>>>(sc);

    // 12) ctx[h] = probs[h] @ v_h  (K clamped by causality)     [2048 x 32 x 128]
    sgemm_kernel<false, 2><<<dim3(1, 16, H_), blk>>>(
        sc, kv + DN_, ctx, T_, DV_, T_,
        T_, H_ * (DN_ + DV_), H_ * DV_,
        (long)T_ * T_, DN_ + DV_, DV_, 1.0f);

    // 13) out = ctx @ wo                           [2048 x 5120]
    sgemm_kernel<false, 0><<<dim3(40, 16, 1), blk>>>(
        ctx, wo, out, T_, HIDDEN_, H_ * DV_,
        H_ * DV_, HIDDEN_, HIDDEN_, 0, 0, 0, 1.0f);
}

// round 2
// speedup vs baseline: 3.4745x; 3.4745x over previous
#include <cuda_runtime.h>
#include <math.h>

// ---------------------------------------------------------------------------
// DeepSeek V2 MLA attention prefill — TF32 tensor-core GEMMs (mma.sync),
// fp32 accumulate. T=2048, H=32, HIDDEN=5120, QL=1536, KVL=512, DQK=192, DV=128.
// ---------------------------------------------------------------------------

namespace {
constexpr int T_      = 2048;
constexpr int H_      = 32;
constexpr int HIDDEN_ = 5120;
constexpr int QL_     = 1536;
constexpr int KVL_    = 512;
constexpr int DN_     = 128;
constexpr int DR_     = 64;
constexpr int DQK_    = 192;
constexpr int DV_     = 128;
constexpr float EPS_  = 1e-6f;
}

// ------------------------- scratch (static device) -------------------------
__device__ float g_qa[(long)T_ * QL_];
__device__ float g_q [(long)T_ * H_ * DQK_];
__device__ float g_ckv[(long)T_ * (KVL_ + DR_)];
__device__ float g_cn [(long)T_ * KVL_];
__device__ float g_kv [(long)T_ * H_ * (DN_ + DV_)];
__device__ float g_kr [(long)T_ * DR_];
__device__ float g_k  [(long)T_ * H_ * DQK_];
__device__ float g_scores[(long)H_ * T_ * T_];
__device__ float g_ctx[(long)T_ * H_ * DV_];

// ------------------------------ helpers ------------------------------------
__device__ __forceinline__ float f2tf32(float x) {
    unsigned u;
    asm("cvt.rna.tf32.f32 %0, %1;" : "=r"(u) : "f"(x));
    return __uint_as_float(u);
}

__device__ __forceinline__ void mma_tf32(float* d, const unsigned* a, const unsigned* b) {
    asm volatile(
        "mma.sync.aligned.m16n8k8.row.col.f32.tf32.tf32.f32 "
        "{%0,%1,%2,%3}, {%4,%5,%6,%7}, {%8,%9}, {%0,%1,%2,%3};"
        : "+f"(d[0]), "+f"(d[1]), "+f"(d[2]), "+f"(d[3])
        : "r"(a[0]), "r"(a[1]), "r"(a[2]), "r"(a[3]),
          "r"(b[0]), "r"(b[1]));
}

// ------------------------------- TF32 GEMM ---------------------------------
// C[M,N] = alpha * A @ B   (NT=false: B is KxN row-major; NT=true: B is NxK)
// CAUSAL: 0 none; 1 skip tiles strictly above diagonal; 2 clamp K to (by+1)*128.
// Block tile 128x128xBK16, 256 threads = 8 warps (4 M x 2 N), warp tile 32x64.
template<bool NT, int CAUSAL>
__global__ __launch_bounds__(256, 2)
void tgemm_kernel(const float* __restrict__ A,
                  const float* __restrict__ B,
                  float* __restrict__ C,
                  int M, int N, int K,
                  int lda, int ldb, int ldc,
                  long sA, long sB, long sC,
                  float alpha)
{
    constexpr int BM = 128, BN = 128, BK = 16;
    constexpr int LDS_ = BM + 4;   // padded row stride (floats)
    const int bx = blockIdx.x, by = blockIdx.y, bz = blockIdx.z;
    if (CAUSAL == 1 && bx > by) return;

    int Keff = K;
    if (CAUSAL == 2) { int lim = (by + 1) * BM; if (lim < Keff) Keff = lim; }

    A += (long)bz * sA;
    B += (long)bz * sB;
    C += (long)bz * sC;

    __shared__ __align__(16) float As[BK][LDS_];   // [k][m], tf32-rounded
    __shared__ __align__(16) float Bs[BK][LDS_];   // [k][n], tf32-rounded

    const int tid  = threadIdx.x;
    const int lane = tid & 31;
    const int warp = tid >> 5;
    const int gid  = lane >> 2;      // 0..7
    const int tig  = lane & 3;       // 0..3
    const int wr   = warp & 3;       // warp row (M)
    const int wc   = warp >> 2;      // warp col (N)
    const int rowBase = by * BM, colBase = bx * BN;
    const int wm = wr * 32;          // warp M offset in tile
    const int wn = wc * 64;          // warp N offset in tile

    float acc[2][8][4];
    #pragma unroll
    for (int i = 0; i < 2; i++)
        #pragma unroll
        for (int j = 0; j < 8; j++)
            #pragma unroll
            for (int v = 0; v < 4; v++) acc[i][j][v] = 0.0f;

    for (int k0 = 0; k0 < Keff; k0 += BK) {
        // ---- A tile: 128 rows x 16 k, rows always in range, K % 16 == 0
        #pragma unroll
        for (int i = 0; i < 2; i++) {
            int f = tid + i * 256;          // 512 float4 total
            int r = f >> 2, c = (f & 3) * 4;
            const float4 v = *reinterpret_cast<const float4*>(
                &A[(long)(rowBase + r) * lda + (k0 + c)]);
            As[c + 0][r] = f2tf32(v.x);
            As[c + 1][r] = f2tf32(v.y);
            As[c + 2][r] = f2tf32(v.z);
            As[c + 3][r] = f2tf32(v.w);
        }
        // ---- B tile
        if (NT) {   // B is [N][K]
            #pragma unroll
            for (int i = 0; i < 2; i++) {
                int f = tid + i * 256;
                int n = f >> 2, c = (f & 3) * 4;
                int gn = colBase + n;
                float4 v = make_float4(0.f, 0.f, 0.f, 0.f);
                if (gn < N)
                    v = *reinterpret_cast<const float4*>(
                        &B[(long)gn * ldb + (k0 + c)]);
                Bs[c + 0][n] = f2tf32(v.x);
                Bs[c + 1][n] = f2tf32(v.y);
                Bs[c + 2][n] = f2tf32(v.z);
                Bs[c + 3][n] = f2tf32(v.w);
            }
        } else {    // B is [K][N]
            #pragma unroll
            for (int i = 0; i < 2; i++) {
                int f = tid + i * 256;
                int r = f >> 5, c = (f & 31) * 4;
                int gc = colBase + c;
                float4 v = make_float4(0.f, 0.f, 0.f, 0.f);
                if (gc + 3 < N) {
                    v = *reinterpret_cast<const float4*>(
                        &B[(long)(k0 + r) * ldb + gc]);
                } else if (gc < N) {
                    v.x = B[(long)(k0 + r) * ldb + gc];
                    if (gc + 1 < N) v.y = B[(long)(k0 + r) * ldb + gc + 1];
                    if (gc + 2 < N) v.z = B[(long)(k0 + r) * ldb + gc + 2];
                }
                float4 t = make_float4(f2tf32(v.x), f2tf32(v.y), f2tf32(v.z), f2tf32(v.w));
                *reinterpret_cast<float4*>(&Bs[r][c]) = t;
            }
        }
        __syncthreads();

        // ---- two k-steps of 8
        #pragma unroll
        for (int ks = 0; ks < BK; ks += 8) {
            unsigned af[2][4];
            #pragma unroll
            for (int mt = 0; mt < 2; mt++) {
                int m0 = wm + mt * 16;
                af[mt][0] = __float_as_uint(As[ks + tig    ][m0 + gid    ]);
                af[mt][1] = __float_as_uint(As[ks + tig    ][m0 + gid + 8]);
                af[mt][2] = __float_as_uint(As[ks + tig + 4][m0 + gid    ]);
                af[mt][3] = __float_as_uint(As[ks + tig + 4][m0 + gid + 8]);
            }
            #pragma unroll
            for (int nt = 0; nt < 8; nt++) {
                int n0 = wn + nt * 8;
                unsigned bf[2];
                bf[0] = __float_as_uint(Bs[ks + tig    ][n0 + gid]);
                bf[1] = __float_as_uint(Bs[ks + tig + 4][n0 + gid]);
                mma_tf32(acc[0][nt], af[0], bf);
                mma_tf32(acc[1][nt], af[1], bf);
            }
        }
        __syncthreads();
    }

    // ---- epilogue: each acc tile holds (row=gid[+8], col=tig*2[+1])
    #pragma unroll
    for (int mt = 0; mt < 2; mt++) {
        #pragma unroll
        for (int nt = 0; nt < 8; nt++) {
            int gc = colBase + wn + nt * 8 + tig * 2;
            #pragma unroll
            for (int half = 0; half < 2; half++) {
                int gr = rowBase + wm + mt * 16 + gid + half * 8;
                float2 v = make_float2(alpha * acc[mt][nt][half * 2],
                                       alpha * acc[mt][nt][half * 2 + 1]);
                if (gc + 1 < N) {
                    *reinterpret_cast<float2*>(&C[(long)gr * ldc + gc]) = v;
                } else if (gc < N) {
                    C[(long)gr * ldc + gc] = v.x;
                }
            }
        }
    }
}

// ------------------------------ RMSNorm ------------------------------------
__global__ void rmsnorm_kernel(const float* __restrict__ x,
                               const float* __restrict__ w,
                               float* __restrict__ y,
                               int L, int ldx, int ldy)
{
    const int row = blockIdx.x, tid = threadIdx.x;
    const float* xr = x + (long)row * ldx;
    float* yr = y + (long)row * ldy;

    __shared__ float red[256];
    float s = 0.0f;
    for (int i = tid; i < L; i += 256) { float v = xr[i]; s += v * v; }
    red[tid] = s; __syncthreads();
    for (int o = 128; o > 0; o >>= 1) {
        if (tid < o) red[tid] += red[tid + o];
        __syncthreads();
    }
    const float scale = rsqrtf(red[0] / (float)L + EPS_);
    for (int i = tid; i < L; i += 256) yr[i] = xr[i] * scale * w[i];
}

// -------------------------------- RoPE -------------------------------------
__global__ void rope_kernel(const float* __restrict__ x, float* __restrict__ o,
                            const float* __restrict__ cosT,
                            const float* __restrict__ sinT,
                            long sxt, int sxh, long sot, int soh)
{
    const int h = blockIdx.x, t = blockIdx.y, i = threadIdx.x;  // i < 64
    const float* xp = x + (long)t * sxt + (long)h * sxh;
    float* op = o + (long)t * sot + (long)h * soh;

    __shared__ float xs[64];
    __shared__ float ys[64];
    xs[i] = xp[i];
    __syncthreads();
    float y = (i < 32) ? xs[2 * i] : xs[2 * (i - 32) + 1];
    ys[i] = y;
    __syncthreads();
    float rot = (i < 32) ? -ys[i + 32] : ys[i - 32];
    op[i] = y * cosT[(long)t * DR_ + i] + rot * sinT[(long)t * DR_ + i];
}

// ------------------------------ build K ------------------------------------
__global__ void build_k_kernel(const float* __restrict__ kv,
                               const float* __restrict__ kr,
                               float* __restrict__ k)
{
    const int h = blockIdx.x, t = blockIdx.y, i = threadIdx.x;  // i < 192
    float v;
    if (i < DN_) v = kv[(long)t * (H_ * (DN_ + DV_)) + h * (DN_ + DV_) + i];
    else         v = kr[(long)t * DR_ + (i - DN_)];
    k[(long)t * (H_ * DQK_) + h * DQK_ + i] = v;
}

// --------------------------- causal softmax --------------------------------
__global__ void softmax_kernel(float* __restrict__ S)
{
    const int i = blockIdx.x, h = blockIdx.y, tid = threadIdx.x;
    float* row = S + ((long)h * T_ + i) * T_;
    const int len = i + 1;

    __shared__ float red[256];

    float m = -3.4e38f;
    for (int j = tid; j < len; j += 256) m = fmaxf(m, row[j]);
    red[tid] = m; __syncthreads();
    for (int o = 128; o > 0; o >>= 1) {
        if (tid < o) red[tid] = fmaxf(red[tid], red[tid + o]);
        __syncthreads();
    }
    m = red[0]; __syncthreads();

    float sum = 0.0f;
    for (int j = tid; j < len; j += 256) {
        float e = expf(row[j] - m);
        row[j] = e;
        sum += e;
    }
    red[tid] = sum; __syncthreads();
    for (int o = 128; o > 0; o >>= 1) {
        if (tid < o) red[tid] += red[tid + o];
        __syncthreads();
    }
    const float inv = 1.0f / red[0];

    for (int j = tid; j < len; j += 256) row[j] *= inv;
    for (int j = len + tid; j < T_; j += 256) row[j] = 0.0f;
}

// ------------------------------- launch ------------------------------------
extern "C" void kernel_launch(void* const* d_in, const int* in_sizes, int n_in,
                              void* d_out, int out_size)
{
    const float* hidden = (const float*)d_in[0];
    const float* cosT   = (const float*)d_in[1];
    const float* sinT   = (const float*)d_in[2];
    const float* wq_a   = (const float*)d_in[3];
    const float* q_ln   = (const float*)d_in[4];
    const float* wq_b   = (const float*)d_in[5];
    const float* wkv_a  = (const float*)d_in[6];
    const float* kv_ln  = (const float*)d_in[7];
    const float* wkv_b  = (const float*)d_in[8];
    const float* wo     = (const float*)d_in[9];
    float* out = (float*)d_out;

    static float *qa = nullptr, *q = nullptr, *ckv = nullptr, *cn = nullptr,
                 *kv = nullptr, *kr = nullptr, *k = nullptr, *sc = nullptr,
                 *ctx = nullptr;
    if (!qa) {
        cudaGetSymbolAddress((void**)&qa,  g_qa);
        cudaGetSymbolAddress((void**)&q,   g_q);
        cudaGetSymbolAddress((void**)&ckv, g_ckv);
        cudaGetSymbolAddress((void**)&cn,  g_cn);
        cudaGetSymbolAddress((void**)&kv,  g_kv);
        cudaGetSymbolAddress((void**)&kr,  g_kr);
        cudaGetSymbolAddress((void**)&k,   g_k);
        cudaGetSymbolAddress((void**)&sc,  g_scores);
        cudaGetSymbolAddress((void**)&ctx, g_ctx);
    }

    const float scaling = 0.07216878364870323f;  // 192^-0.5
    const dim3 blk(256);

    // 1) q_a = hidden @ wq_a                       [2048 x 1536]
    tgemm_kernel<false, 0><<<dim3(12, 16, 1), blk>>>(
        hidden, wq_a, qa, T_, QL_, HIDDEN_, HIDDEN_, QL_, QL_, 0, 0, 0, 1.0f);

    // 2) rmsnorm(q_a) in place
    rmsnorm_kernel<<<T_, 256>>>(qa, q_ln, qa, QL_, QL_, QL_);

    // 3) q = q_a_n @ wq_b                          [2048 x 6144]
    tgemm_kernel<false, 0><<<dim3(48, 16, 1), blk>>>(
        qa, wq_b, q, T_, H_ * DQK_, QL_, QL_, H_ * DQK_, H_ * DQK_, 0, 0, 0, 1.0f);

    // 4) ckv = hidden @ wkv_a                      [2048 x 576]
    tgemm_kernel<false, 0><<<dim3(5, 16, 1), blk>>>(
        hidden, wkv_a, ckv, T_, KVL_ + DR_, HIDDEN_,
        HIDDEN_, KVL_ + DR_, KVL_ + DR_, 0, 0, 0, 1.0f);

    // 5) cn = rmsnorm(ckv[:, :512])
    rmsnorm_kernel<<<T_, 256>>>(ckv, kv_ln, cn, KVL_, KVL_ + DR_, KVL_);

    // 6) kv = cn @ wkv_b                           [2048 x 8192]
    tgemm_kernel<false, 0><<<dim3(64, 16, 1), blk>>>(
        cn, wkv_b, kv, T_, H_ * (DN_ + DV_), KVL_,
        KVL_, H_ * (DN_ + DV_), H_ * (DN_ + DV_), 0, 0, 0, 1.0f);

    // 7) RoPE on q_pe (in place)
    rope_kernel<<<dim3(H_, T_), 64>>>(q + DN_, q + DN_, cosT, sinT,
                                      H_ * DQK_, DQK_, H_ * DQK_, DQK_);

    // 8) RoPE on k_pe -> kr
    rope_kernel<<<dim3(1, T_), 64>>>(ckv + KVL_, kr, cosT, sinT,
                                     KVL_ + DR_, 0, DR_, 0);

    // 9) assemble K = [k_nope | broadcast k_rope]
    build_k_kernel<<<dim3(H_, T_), 192>>>(kv, kr, k);

    // 10) scores[h] = scaling * q_h @ k_h^T (causal tile skip)
    tgemm_kernel<true, 1><<<dim3(16, 16, H_), blk>>>(
        q, k, sc, T_, T_, DQK_,
        H_ * DQK_, H_ * DQK_, T_,
        DQK_, DQK_, (long)T_ * T_, scaling);

    // 11) causal softmax
    softmax_kernel<<<dim3(T_, H_), 256>>>(sc);

    // 12) ctx[h] = probs[h] @ v_h  (K clamped by causality)
    tgemm_kernel<false, 2><<<dim3(1, 16, H_), blk>>>(
        sc, kv + DN_, ctx, T_, DV_, T_,
        T_, H_ * (DN_ + DV_), H_ * DV_,
        (long)T_ * T_, DN_ + DV_, DV_, 1.0f);

    // 13) out = ctx @ wo                           [2048 x 5120]
    tgemm_kernel<false, 0><<<dim3(40, 16, 1), blk>>>(
        ctx, wo, out, T_, HIDDEN_, H_ * DV_,
        H_ * DV_, HIDDEN_, HIDDEN_, 0, 0, 0, 1.0f);
}

// round 3
// speedup vs baseline: 6.5056x; 1.8723x over previous
#include <cuda_runtime.h>
#include <math.h>

// ---------------------------------------------------------------------------
// DeepSeek V2 MLA attention prefill — TF32 tensor-core GEMMs with 4-stage
// cp.async pipeline. T=2048, H=32, HIDDEN=5120, QL=1536, KVL=512.
// ---------------------------------------------------------------------------

namespace {
constexpr int T_      = 2048;
constexpr int H_      = 32;
constexpr int HIDDEN_ = 5120;
constexpr int QL_     = 1536;
constexpr int KVL_    = 512;
constexpr int DN_     = 128;
constexpr int DR_     = 64;
constexpr int DQK_    = 192;
constexpr int DV_     = 128;
constexpr float EPS_  = 1e-6f;
constexpr int SMEM_BYTES = 4 * (2560 + 2560) * 4;   // 80 KB
}

// ------------------------- scratch (static device) -------------------------
__device__ float g_qa[(long)T_ * QL_];
__device__ float g_q [(long)T_ * H_ * DQK_];
__device__ float g_ckv[(long)T_ * (KVL_ + DR_)];
__device__ float g_cn [(long)T_ * KVL_];
__device__ float g_kv [(long)T_ * H_ * (DN_ + DV_)];
__device__ float g_kr [(long)T_ * DR_];
__device__ float g_k  [(long)T_ * H_ * DQK_];
__device__ float g_scores[(long)H_ * T_ * T_];
__device__ float g_ctx[(long)T_ * H_ * DV_];

// ------------------------------ helpers ------------------------------------
__device__ __forceinline__ unsigned f2tf32u(float x) {
    unsigned u;
    asm("cvt.rna.tf32.f32 %0, %1;" : "=r"(u) : "f"(x));
    return u;
}

__device__ __forceinline__ void mma_tf32(float* d, const unsigned* a, const unsigned* b) {
    asm volatile(
        "mma.sync.aligned.m16n8k8.row.col.f32.tf32.tf32.f32 "
        "{%0,%1,%2,%3}, {%4,%5,%6,%7}, {%8,%9}, {%0,%1,%2,%3};"
        : "+f"(d[0]), "+f"(d[1]), "+f"(d[2]), "+f"(d[3])
        : "r"(a[0]), "r"(a[1]), "r"(a[2]), "r"(a[3]),
          "r"(b[0]), "r"(b[1]));
}

__device__ __forceinline__ unsigned smem_u32(const void* p) {
    return (unsigned)__cvta_generic_to_shared(p);
}

__device__ __forceinline__ void cp16(unsigned dst, const void* src) {
    asm volatile("cp.async.cg.shared.global [%0], [%1], 16;\n"
                 :: "r"(dst), "l"(src));
}

__device__ __forceinline__ void cp16z(unsigned dst, const void* src, int srcsize) {
    asm volatile("cp.async.cg.shared.global [%0], [%1], 16, %2;\n"
                 :: "r"(dst), "l"(src), "r"(srcsize));
}

// ------------------------------- TF32 GEMM ---------------------------------
// C[M,N] = alpha * A @ B   (NT=false: B is KxN row-major; NT=true: B is NxK)
// CAUSAL: 0 none; 1 skip tiles strictly above diagonal; 2 clamp K to (by+1)*128.
// Block tile 128x128x16, 256 threads = 8 warps (4 M x 2 N), warp tile 32x64.
// 4-stage cp.async pipeline; tf32 conversion at fragment-load time.
template<bool NT, int CAUSAL>
__global__ __launch_bounds__(256, 2)
void tgemm_kernel(const float* __restrict__ A,
                  const float* __restrict__ B,
                  float* __restrict__ C,
                  int M, int N, int K,
                  int lda, int ldb, int ldc,
                  long sA, long sB, long sC,
                  float alpha)
{
    constexpr int BM = 128, BN = 128, BK = 16, S = 4;
    constexpr int APAD = 20;       // A row stride (floats), conflict-free frags
    constexpr int BPAD_KN = 136;   // B[K][N] row stride
    constexpr int BPAD_NT = 20;    // B[N][K] row stride
    constexpr int ASTAGE = BM * APAD;   // 2560 floats
    constexpr int BSTAGE = 2560;        // max(16*136, 128*20)

    const int bx = blockIdx.x, by = blockIdx.y, bz = blockIdx.z;
    if (CAUSAL == 1 && bx > by) return;

    int Keff = K;
    if (CAUSAL == 2) { int lim = (by + 1) * BM; if (lim < Keff) Keff = lim; }

    A += (long)bz * sA;
    B += (long)bz * sB;
    C += (long)bz * sC;

    extern __shared__ float smem[];
    float* As = smem;
    float* Bs = smem + S * ASTAGE;

    const int tid  = threadIdx.x;
    const int lane = tid & 31;
    const int warp = tid >> 5;
    const int gid  = lane >> 2;
    const int tig  = lane & 3;
    const int wr   = warp & 3;
    const int wc   = warp >> 2;
    const int rowBase = by * BM, colBase = bx * BN;
    const int wm = wr * 32, wn = wc * 64;

    const int tiles = Keff / BK;

    auto load_tile = [&](int st, int kt) {
        const int k0 = kt * BK;
        // A: 128 rows x 16 k = 512 16B chunks, 2 per thread (always in-range)
        #pragma unroll
        for (int i = 0; i < 2; i++) {
            int c = tid + i * 256;
            int r = c >> 2, kc = (c & 3) * 4;
            unsigned dst = smem_u32(&As[st * ASTAGE + r * APAD + kc]);
            cp16(dst, &A[(long)(rowBase + r) * lda + (k0 + kc)]);
        }
        if (NT) {
            // B[N][K]: 128 n-rows x 16 k
            #pragma unroll
            for (int i = 0; i < 2; i++) {
                int c = tid + i * 256;
                int n = c >> 2, kc = (c & 3) * 4;
                int gn = colBase + n;
                unsigned dst = smem_u32(&Bs[st * BSTAGE + n * BPAD_NT + kc]);
                const float* src = &B[(long)(gn < N ? gn : 0) * ldb + (k0 + kc)];
                cp16z(dst, src, gn < N ? 16 : 0);
            }
        } else {
            // B[K][N]: 16 k-rows x 128 n  (N always multiple of 4 here)
            #pragma unroll
            for (int i = 0; i < 2; i++) {
                int c = tid + i * 256;
                int r = c >> 5, nc = (c & 31) * 4;
                int gc = colBase + nc;
                unsigned dst = smem_u32(&Bs[st * BSTAGE + r * BPAD_KN + nc]);
                const float* src = &B[(long)(k0 + r) * ldb + (gc < N ? gc : 0)];
                cp16z(dst, src, gc < N ? 16 : 0);
            }
        }
    };

    // ---- prologue: fill S-1 stages
    #pragma unroll
    for (int s = 0; s < S - 1; s++) {
        if (s < tiles) load_tile(s, s);
        asm volatile("cp.async.commit_group;\n");
    }

    float acc[2][8][4];
    #pragma unroll
    for (int i = 0; i < 2; i++)
        #pragma unroll
        for (int j = 0; j < 8; j++)
            #pragma unroll
            for (int v = 0; v < 4; v++) acc[i][j][v] = 0.0f;

    for (int t = 0; t < tiles; t++) {
        asm volatile("cp.async.wait_group %0;\n" :: "n"(S - 2));
        __syncthreads();

        int tn = t + S - 1;
        if (tn < tiles) load_tile(tn % S, tn);
        asm volatile("cp.async.commit_group;\n");

        const int st = t % S;
        const float* Asb = &As[st * ASTAGE];
        const float* Bsb = &Bs[st * BSTAGE];

        #pragma unroll
        for (int ks = 0; ks < 2; ks++) {
            const int kb = ks * 8;
            unsigned af[2][4];
            #pragma unroll
            for (int mt = 0; mt < 2; mt++) {
                int m0 = wm + mt * 16;
                af[mt][0] = f2tf32u(Asb[(m0 + gid    ) * APAD + kb + tig    ]);
                af[mt][1] = f2tf32u(Asb[(m0 + gid + 8) * APAD + kb + tig    ]);
                af[mt][2] = f2tf32u(Asb[(m0 + gid    ) * APAD + kb + tig + 4]);
                af[mt][3] = f2tf32u(Asb[(m0 + gid + 8) * APAD + kb + tig + 4]);
            }
            #pragma unroll
            for (int nt = 0; nt < 8; nt++) {
                int n0 = wn + nt * 8;
                unsigned bf[2];
                if (NT) {
                    bf[0] = f2tf32u(Bsb[(n0 + gid) * BPAD_NT + kb + tig    ]);
                    bf[1] = f2tf32u(Bsb[(n0 + gid) * BPAD_NT + kb + tig + 4]);
                } else {
                    bf[0] = f2tf32u(Bsb[(kb + tig    ) * BPAD_KN + n0 + gid]);
                    bf[1] = f2tf32u(Bsb[(kb + tig + 4) * BPAD_KN + n0 + gid]);
                }
                mma_tf32(acc[0][nt], af[0], bf);
                mma_tf32(acc[1][nt], af[1], bf);
            }
        }
    }

    // ---- epilogue
    #pragma unroll
    for (int mt = 0; mt < 2; mt++) {
        #pragma unroll
        for (int nt = 0; nt < 8; nt++) {
            int gc = colBase + wn + nt * 8 + tig * 2;
            #pragma unroll
            for (int half = 0; half < 2; half++) {
                int gr = rowBase + wm + mt * 16 + gid + half * 8;
                float2 v = make_float2(alpha * acc[mt][nt][half * 2],
                                       alpha * acc[mt][nt][half * 2 + 1]);
                if (gc + 1 < N) {
                    *reinterpret_cast<float2*>(&C[(long)gr * ldc + gc]) = v;
                } else if (gc < N) {
                    C[(long)gr * ldc + gc] = v.x;
                }
            }
        }
    }
}

// ------------------------------ RMSNorm ------------------------------------
__global__ void rmsnorm_kernel(const float* __restrict__ x,
                               const float* __restrict__ w,
                               float* __restrict__ y,
                               int L, int ldx, int ldy)
{
    const int row = blockIdx.x, tid = threadIdx.x;
    const float* xr = x + (long)row * ldx;
    float* yr = y + (long)row * ldy;

    __shared__ float red[256];
    float s = 0.0f;
    for (int i = tid; i < L; i += 256) { float v = xr[i]; s += v * v; }
    red[tid] = s; __syncthreads();
    for (int o = 128; o > 0; o >>= 1) {
        if (tid < o) red[tid] += red[tid + o];
        __syncthreads();
    }
    const float scale = rsqrtf(red[0] / (float)L + EPS_);
    for (int i = tid; i < L; i += 256) yr[i] = xr[i] * scale * w[i];
}

// -------------------------------- RoPE -------------------------------------
__global__ void rope_kernel(const float* __restrict__ x, float* __restrict__ o,
                            const float* __restrict__ cosT,
                            const float* __restrict__ sinT,
                            long sxt, int sxh, long sot, int soh)
{
    const int h = blockIdx.x, t = blockIdx.y, i = threadIdx.x;  // i < 64
    const float* xp = x + (long)t * sxt + (long)h * sxh;
    float* op = o + (long)t * sot + (long)h * soh;

    __shared__ float xs[64];
    __shared__ float ys[64];
    xs[i] = xp[i];
    __syncthreads();
    float y = (i < 32) ? xs[2 * i] : xs[2 * (i - 32) + 1];
    ys[i] = y;
    __syncthreads();
    float rot = (i < 32) ? -ys[i + 32] : ys[i - 32];
    op[i] = y * cosT[(long)t * DR_ + i] + rot * sinT[(long)t * DR_ + i];
}

// ------------------------------ build K ------------------------------------
__global__ void build_k_kernel(const float* __restrict__ kv,
                               const float* __restrict__ kr,
                               float* __restrict__ k)
{
    const int h = blockIdx.x, t = blockIdx.y, i = threadIdx.x;  // i < 192
    float v;
    if (i < DN_) v = kv[(long)t * (H_ * (DN_ + DV_)) + h * (DN_ + DV_) + i];
    else         v = kr[(long)t * DR_ + (i - DN_)];
    k[(long)t * (H_ * DQK_) + h * DQK_ + i] = v;
}

// --------------------------- causal softmax --------------------------------
__global__ void softmax_kernel(float* __restrict__ S)
{
    const int i = blockIdx.x, h = blockIdx.y, tid = threadIdx.x;
    float* row = S + ((long)h * T_ + i) * T_;
    const int len = i + 1;

    __shared__ float red[256];

    float m = -3.4e38f;
    for (int j = tid; j < len; j += 256) m = fmaxf(m, row[j]);
    red[tid] = m; __syncthreads();
    for (int o = 128; o > 0; o >>= 1) {
        if (tid < o) red[tid] = fmaxf(red[tid], red[tid + o]);
        __syncthreads();
    }
    m = red[0]; __syncthreads();

    float sum = 0.0f;
    for (int j = tid; j < len; j += 256) {
        float e = expf(row[j] - m);
        row[j] = e;
        sum += e;
    }
    red[tid] = sum; __syncthreads();
    for (int o = 128; o > 0; o >>= 1) {
        if (tid < o) red[tid] += red[tid + o];
        __syncthreads();
    }
    const float inv = 1.0f / red[0];

    for (int j = tid; j < len; j += 256) row[j] *= inv;
    for (int j = len + tid; j < T_; j += 256) row[j] = 0.0f;
}

// ------------------------------- launch ------------------------------------
extern "C" void kernel_launch(void* const* d_in, const int* in_sizes, int n_in,
                              void* d_out, int out_size)
{
    const float* hidden = (const float*)d_in[0];
    const float* cosT   = (const float*)d_in[1];
    const float* sinT   = (const float*)d_in[2];
    const float* wq_a   = (const float*)d_in[3];
    const float* q_ln   = (const float*)d_in[4];
    const float* wq_b   = (const float*)d_in[5];
    const float* wkv_a  = (const float*)d_in[6];
    const float* kv_ln  = (const float*)d_in[7];
    const float* wkv_b  = (const float*)d_in[8];
    const float* wo     = (const float*)d_in[9];
    float* out = (float*)d_out;

    static float *qa = nullptr, *q = nullptr, *ckv = nullptr, *cn = nullptr,
                 *kv = nullptr, *kr = nullptr, *k = nullptr, *sc = nullptr,
                 *ctx = nullptr;
    if (!qa) {
        cudaGetSymbolAddress((void**)&qa,  g_qa);
        cudaGetSymbolAddress((void**)&q,   g_q);
        cudaGetSymbolAddress((void**)&ckv, g_ckv);
        cudaGetSymbolAddress((void**)&cn,  g_cn);
        cudaGetSymbolAddress((void**)&kv,  g_kv);
        cudaGetSymbolAddress((void**)&kr,  g_kr);
        cudaGetSymbolAddress((void**)&k,   g_k);
        cudaGetSymbolAddress((void**)&sc,  g_scores);
        cudaGetSymbolAddress((void**)&ctx, g_ctx);
        cudaFuncSetAttribute(tgemm_kernel<false, 0>,
                             cudaFuncAttributeMaxDynamicSharedMemorySize, SMEM_BYTES);
        cudaFuncSetAttribute(tgemm_kernel<true, 1>,
                             cudaFuncAttributeMaxDynamicSharedMemorySize, SMEM_BYTES);
        cudaFuncSetAttribute(tgemm_kernel<false, 2>,
                             cudaFuncAttributeMaxDynamicSharedMemorySize, SMEM_BYTES);
    }

    const float scaling = 0.07216878364870323f;  // 192^-0.5
    const dim3 blk(256);

    // 1) q_a = hidden @ wq_a                       [2048 x 1536]
    tgemm_kernel<false, 0><<<dim3(12, 16, 1), blk, SMEM_BYTES>>>(
        hidden, wq_a, qa, T_, QL_, HIDDEN_, HIDDEN_, QL_, QL_, 0, 0, 0, 1.0f);

    // 2) rmsnorm(q_a) in place
    rmsnorm_kernel<<<T_, 256>>>(qa, q_ln, qa, QL_, QL_, QL_);

    // 3) q = q_a_n @ wq_b                          [2048 x 6144]
    tgemm_kernel<false, 0><<<dim3(48, 16, 1), blk, SMEM_BYTES>>>(
        qa, wq_b, q, T_, H_ * DQK_, QL_, QL_, H_ * DQK_, H_ * DQK_, 0, 0, 0, 1.0f);

    // 4) ckv = hidden @ wkv_a                      [2048 x 576]
    tgemm_kernel<false, 0><<<dim3(5, 16, 1), blk, SMEM_BYTES>>>(
        hidden, wkv_a, ckv, T_, KVL_ + DR_, HIDDEN_,
        HIDDEN_, KVL_ + DR_, KVL_ + DR_, 0, 0, 0, 1.0f);

    // 5) cn = rmsnorm(ckv[:, :512])
    rmsnorm_kernel<<<T_, 256>>>(ckv, kv_ln, cn, KVL_, KVL_ + DR_, KVL_);

    // 6) kv = cn @ wkv_b                           [2048 x 8192]
    tgemm_kernel<false, 0><<<dim3(64, 16, 1), blk, SMEM_BYTES>>>(
        cn, wkv_b, kv, T_, H_ * (DN_ + DV_), KVL_,
        KVL_, H_ * (DN_ + DV_), H_ * (DN_ + DV_), 0, 0, 0, 1.0f);

    // 7) RoPE on q_pe (in place)
    rope_kernel<<<dim3(H_, T_), 64>>>(q + DN_, q + DN_, cosT, sinT,
                                      H_ * DQK_, DQK_, H_ * DQK_, DQK_);

    // 8) RoPE on k_pe -> kr
    rope_kernel<<<dim3(1, T_), 64>>>(ckv + KVL_, kr, cosT, sinT,
                                     KVL_ + DR_, 0, DR_, 0);

    // 9) assemble K = [k_nope | broadcast k_rope]
    build_k_kernel<<<dim3(H_, T_), 192>>>(kv, kr, k);

    // 10) scores[h] = scaling * q_h @ k_h^T (causal tile skip)
    tgemm_kernel<true, 1><<<dim3(16, 16, H_), blk, SMEM_BYTES>>>(
        q, k, sc, T_, T_, DQK_,
        H_ * DQK_, H_ * DQK_, T_,
        DQK_, DQK_, (long)T_ * T_, scaling);

    // 11) causal softmax
    softmax_kernel<<<dim3(T_, H_), 256>>>(sc);

    // 12) ctx[h] = probs[h] @ v_h  (K clamped by causality)
    tgemm_kernel<false, 2><<<dim3(1, 16, H_), blk, SMEM_BYTES>>>(
        sc, kv + DN_, ctx, T_, DV_, T_,
        T_, H_ * (DN_ + DV_), H_ * DV_,
        (long)T_ * T_, DN_ + DV_, DV_, 1.0f);

    // 13) out = ctx @ wo                           [2048 x 5120]
    tgemm_kernel<false, 0><<<dim3(40, 16, 1), blk, SMEM_BYTES>>>(
        ctx, wo, out, T_, HIDDEN_, H_ * DV_,
        H_ * DV_, HIDDEN_, HIDDEN_, 0, 0, 0, 1.0f);
}

// round 4
// speedup vs baseline: 7.0274x; 1.0802x over previous
#include <cuda_runtime.h>
#include <math.h>

// ---------------------------------------------------------------------------
// DeepSeek V2 MLA attention prefill — TF32 mma GEMMs (cp.async pipelined) +
// fused flash-attention (QK^T -> online softmax -> PV) per (head, q-tile).
// ---------------------------------------------------------------------------

namespace {
constexpr int T_      = 2048;
constexpr int H_      = 32;
constexpr int HIDDEN_ = 5120;
constexpr int QL_     = 1536;
constexpr int KVL_    = 512;
constexpr int DN_     = 128;
constexpr int DR_     = 64;
constexpr int DQK_    = 192;
constexpr int DV_     = 128;
constexpr float EPS_  = 1e-6f;
constexpr float SCALING_ = 0.07216878364870323f;  // 192^-0.5
constexpr int SMEM_BYTES = 4 * (2560 + 2560) * 4;   // 80 KB (dense GEMM)

// fused attention smem layout (floats)
constexpr int QPAD  = 204;                 // Q row stride
constexpr int KPAD  = 20;                  // K chunk row stride [key][16d]
constexpr int VPAD  = 136;                 // V chunk row stride [16k][128n]
constexpr int PPAD  = 132;                 // P row stride [m][key]
constexpr int QS_F  = 128 * QPAD;          // 26112
constexpr int STG_F = 2560;                // per KV stage (max 128*20, 16*136)
constexpr int PS_F  = 128 * PPAD;          // 16896
constexpr int FUSED_F = QS_F + 3 * STG_F + PS_F + 3 * 128 + 256;  // 51328
constexpr int FUSED_SMEM = FUSED_F * 4;    // 205312 B
}

// ------------------------- scratch (static device) -------------------------
__device__ float g_qa[(long)T_ * QL_];
__device__ float g_q [(long)T_ * H_ * DQK_];
__device__ float g_ckv[(long)T_ * (KVL_ + DR_)];
__device__ float g_cn [(long)T_ * KVL_];
__device__ float g_kv [(long)T_ * H_ * (DN_ + DV_)];
__device__ float g_kr [(long)T_ * DR_];
__device__ float g_ctx[(long)T_ * H_ * DV_];

// ------------------------------ helpers ------------------------------------
__device__ __forceinline__ unsigned f2tf32u(float x) {
    unsigned u;
    asm("cvt.rna.tf32.f32 %0, %1;" : "=r"(u) : "f"(x));
    return u;
}

__device__ __forceinline__ void mma_tf32(float* d, const unsigned* a, const unsigned* b) {
    asm volatile(
        "mma.sync.aligned.m16n8k8.row.col.f32.tf32.tf32.f32 "
        "{%0,%1,%2,%3}, {%4,%5,%6,%7}, {%8,%9}, {%0,%1,%2,%3};"
        : "+f"(d[0]), "+f"(d[1]), "+f"(d[2]), "+f"(d[3])
        : "r"(a[0]), "r"(a[1]), "r"(a[2]), "r"(a[3]),
          "r"(b[0]), "r"(b[1]));
}

__device__ __forceinline__ unsigned smem_u32(const void* p) {
    return (unsigned)__cvta_generic_to_shared(p);
}

__device__ __forceinline__ void cp16(unsigned dst, const void* src) {
    asm volatile("cp.async.cg.shared.global [%0], [%1], 16;\n"
                 :: "r"(dst), "l"(src));
}

__device__ __forceinline__ void cp16z(unsigned dst, const void* src, int srcsize) {
    asm volatile("cp.async.cg.shared.global [%0], [%1], 16, %2;\n"
                 :: "r"(dst), "l"(src), "r"(srcsize));
}

// ------------------------------- TF32 GEMM ---------------------------------
// C[M,N] = A @ B  (B is KxN row-major). 128x128x16 tile, 4-stage cp.async.
__global__ __launch_bounds__(256, 2)
void tgemm_kernel(const float* __restrict__ A,
                  const float* __restrict__ B,
                  float* __restrict__ C,
                  int M, int N, int K,
                  int lda, int ldb, int ldc)
{
    constexpr int BM = 128, BK = 16, S = 4;
    constexpr int APAD = 20;
    constexpr int BPAD_KN = 136;
    constexpr int ASTAGE = BM * APAD;
    constexpr int BSTAGE = 2560;

    const int bx = blockIdx.x, by = blockIdx.y;

    extern __shared__ float smem[];
    float* As = smem;
    float* Bs = smem + S * ASTAGE;

    const int tid  = threadIdx.x;
    const int lane = tid & 31;
    const int warp = tid >> 5;
    const int gid  = lane >> 2;
    const int tig  = lane & 3;
    const int wr   = warp & 3;
    const int wc   = warp >> 2;
    const int rowBase = by * BM, colBase = bx * 128;
    const int wm = wr * 32, wn = wc * 64;

    const int tiles = K / BK;

    auto load_tile = [&](int st, int kt) {
        const int k0 = kt * BK;
        #pragma unroll
        for (int i = 0; i < 2; i++) {
            int c = tid + i * 256;
            int r = c >> 2, kc = (c & 3) * 4;
            cp16(smem_u32(&As[st * ASTAGE + r * APAD + kc]),
                 &A[(long)(rowBase + r) * lda + (k0 + kc)]);
        }
        #pragma unroll
        for (int i = 0; i < 2; i++) {
            int c = tid + i * 256;
            int r = c >> 5, nc = (c & 31) * 4;
            int gc = colBase + nc;
            const float* src = &B[(long)(k0 + r) * ldb + (gc < N ? gc : 0)];
            cp16z(smem_u32(&Bs[st * BSTAGE + r * BPAD_KN + nc]), src,
                  gc < N ? 16 : 0);
        }
    };

    #pragma unroll
    for (int s = 0; s < S - 1; s++) {
        if (s < tiles) load_tile(s, s);
        asm volatile("cp.async.commit_group;\n");
    }

    float acc[2][8][4];
    #pragma unroll
    for (int i = 0; i < 2; i++)
        #pragma unroll
        for (int j = 0; j < 8; j++)
            #pragma unroll
            for (int v = 0; v < 4; v++) acc[i][j][v] = 0.0f;

    for (int t = 0; t < tiles; t++) {
        asm volatile("cp.async.wait_group %0;\n" :: "n"(S - 2));
        __syncthreads();

        int tn = t + S - 1;
        if (tn < tiles) load_tile(tn % S, tn);
        asm volatile("cp.async.commit_group;\n");

        const int st = t % S;
        const float* Asb = &As[st * ASTAGE];
        const float* Bsb = &Bs[st * BSTAGE];

        #pragma unroll
        for (int ks = 0; ks < 2; ks++) {
            const int kb = ks * 8;
            unsigned af[2][4];
            #pragma unroll
            for (int mt = 0; mt < 2; mt++) {
                int m0 = wm + mt * 16;
                af[mt][0] = f2tf32u(Asb[(m0 + gid    ) * APAD + kb + tig    ]);
                af[mt][1] = f2tf32u(Asb[(m0 + gid + 8) * APAD + kb + tig    ]);
                af[mt][2] = f2tf32u(Asb[(m0 + gid    ) * APAD + kb + tig + 4]);
                af[mt][3] = f2tf32u(Asb[(m0 + gid + 8) * APAD + kb + tig + 4]);
            }
            #pragma unroll
            for (int nt = 0; nt < 8; nt++) {
                int n0 = wn + nt * 8;
                unsigned bf[2];
                bf[0] = f2tf32u(Bsb[(kb + tig    ) * BPAD_KN + n0 + gid]);
                bf[1] = f2tf32u(Bsb[(kb + tig + 4) * BPAD_KN + n0 + gid]);
                mma_tf32(acc[0][nt], af[0], bf);
                mma_tf32(acc[1][nt], af[1], bf);
            }
        }
    }

    #pragma unroll
    for (int mt = 0; mt < 2; mt++) {
        #pragma unroll
        for (int nt = 0; nt < 8; nt++) {
            int gc = colBase + wn + nt * 8 + tig * 2;
            #pragma unroll
            for (int half = 0; half < 2; half++) {
                int gr = rowBase + wm + mt * 16 + gid + half * 8;
                float2 v = make_float2(acc[mt][nt][half * 2],
                                       acc[mt][nt][half * 2 + 1]);
                if (gc + 1 < N) {
                    *reinterpret_cast<float2*>(&C[(long)gr * ldc + gc]) = v;
                } else if (gc < N) {
                    C[(long)gr * ldc + gc] = v.x;
                }
            }
        }
    }
}

// --------------------- fused flash attention kernel ------------------------
// One CTA per (q-tile 128 rows, head). Q resident in smem; K streamed in
// 16-d chunks, V in 16-key chunks through a 3-stage cp.async ring.
__global__ __launch_bounds__(256, 1)
void fused_attn_kernel(const float* __restrict__ q,
                       const float* __restrict__ kv,
                       const float* __restrict__ kr,
                       float* __restrict__ ctx)
{
    extern __shared__ float sm[];
    float* Qs     = sm;                      // 128 x QPAD
    float* KV     = sm + QS_F;               // 3 stages x 2560
    float* Ps     = sm + QS_F + 3 * STG_F;   // 128 x PPAD
    float* row_m  = Ps + PS_F;
    float* row_l  = row_m + 128;
    float* row_r  = row_l + 128;
    float* rowred = row_r + 128;             // [2][128]

    const int qt = 15 - blockIdx.x;          // heavy tiles first
    const int h  = blockIdx.y;
    const long q0 = (long)qt * 128;

    const int tid  = threadIdx.x;
    const int lane = tid & 31;
    const int warp = tid >> 5;
    const int gid  = lane >> 2;
    const int tig  = lane & 3;
    const int wr   = warp & 3;
    const int wc   = warp >> 2;
    const int wm = wr * 32, wn = wc * 64;
    const int KVROW = H_ * (DN_ + DV_);

    if (tid < 128) { row_m[tid] = -1e30f; row_l[tid] = 0.0f; }

    // ---- load Q tile [128 x 192] (one group)
    const float* Qbase = q + q0 * (H_ * DQK_) + h * DQK_;
    #pragma unroll
    for (int i = 0; i < 24; i++) {
        int e = tid + i * 256;          // 0..6143 float4s
        int r = e / 48;
        int fc = (e % 48) * 4;
        cp16(smem_u32(&Qs[r * QPAD + fc]), Qbase + (long)r * (H_ * DQK_) + fc);
    }
    asm volatile("cp.async.commit_group;\n");

    float Oacc[2][8][4];
    #pragma unroll
    for (int i = 0; i < 2; i++)
        #pragma unroll
        for (int j = 0; j < 8; j++)
            #pragma unroll
            for (int v = 0; v < 4; v++) Oacc[i][j][v] = 0.0f;

    for (int j = 0; j <= qt; j++) {
        const long key0 = (long)j * 128;
        const bool diag = (j == qt);

        auto load_k = [&](int st, int c) {
            const int d0 = c * 16;
            float* dst = &KV[st * STG_F];
            #pragma unroll
            for (int i = 0; i < 2; i++) {
                int e = tid + i * 256;
                int r = e >> 2;
                int fc = (e & 3) * 4;
                const float* src = (d0 < DN_)
                    ? kv + (key0 + r) * (long)KVROW + h * (DN_ + DV_) + d0 + fc
                    : kr + (key0 + r) * (long)DR_ + (d0 - DN_) + fc;
                cp16(smem_u32(dst + r * KPAD + fc), src);
            }
        };
        auto load_v = [&](int st, int c) {
            float* dst = &KV[st * STG_F];
            #pragma unroll
            for (int i = 0; i < 2; i++) {
                int e = tid + i * 256;
                int r = e >> 5;
                int fc = (e & 31) * 4;
                const float* src = kv + (key0 + c * 16 + r) * (long)KVROW
                                   + h * (DN_ + DV_) + DN_ + fc;
                cp16(smem_u32(dst + r * VPAD + fc), src);
            }
        };

        float Sacc[2][8][4];
        #pragma unroll
        for (int i = 0; i < 2; i++)
            #pragma unroll
            for (int jj = 0; jj < 8; jj++)
                #pragma unroll
                for (int v = 0; v < 4; v++) Sacc[i][jj][v] = 0.0f;

        // ---- S = Q @ K^T, streaming 12 d-chunks of 16
        load_k(0, 0);
        asm volatile("cp.async.commit_group;\n");
        for (int c = 0; c < 12; c++) {
            if (c + 1 < 12) {
                load_k((c + 1) % 3, c + 1);
                asm volatile("cp.async.commit_group;\n");
                asm volatile("cp.async.wait_group 1;\n");
            } else {
                asm volatile("cp.async.wait_group 0;\n");
            }
            __syncthreads();
            const float* Ks = &KV[(c % 3) * STG_F];
            const int dbase = c * 16;
            #pragma unroll
            for (int ks = 0; ks < 2; ks++) {
                const int kb = ks * 8;
                unsigned af[2][4];
                #pragma unroll
                for (int mt = 0; mt < 2; mt++) {
                    int m0 = wm + mt * 16;
                    af[mt][0] = f2tf32u(Qs[(m0 + gid    ) * QPAD + dbase + kb + tig    ]);
                    af[mt][1] = f2tf32u(Qs[(m0 + gid + 8) * QPAD + dbase + kb + tig    ]);
                    af[mt][2] = f2tf32u(Qs[(m0 + gid    ) * QPAD + dbase + kb + tig + 4]);
                    af[mt][3] = f2tf32u(Qs[(m0 + gid + 8) * QPAD + dbase + kb + tig + 4]);
                }
                #pragma unroll
                for (int nt = 0; nt < 8; nt++) {
                    int n0 = wn + nt * 8;
                    unsigned bf[2];
                    bf[0] = f2tf32u(Ks[(n0 + gid) * KPAD + kb + tig    ]);
                    bf[1] = f2tf32u(Ks[(n0 + gid) * KPAD + kb + tig + 4]);
                    mma_tf32(Sacc[0][nt], af[0], bf);
                    mma_tf32(Sacc[1][nt], af[1], bf);
                }
            }
        }

        // prefetch V chunk 0 (stage 12%3 = 0) — overlaps softmax
        load_v(0, 0);
        asm volatile("cp.async.commit_group;\n");

        // ---- scale + causal mask (in place)
        #pragma unroll
        for (int mt = 0; mt < 2; mt++)
            #pragma unroll
            for (int nt = 0; nt < 8; nt++)
                #pragma unroll
                for (int v = 0; v < 4; v++) {
                    int rl = wm + mt * 16 + (v >> 1) * 8 + gid;
                    int cl = wn + nt * 8 + tig * 2 + (v & 1);
                    float s = Sacc[mt][nt][v] * SCALING_;
                    if (diag && cl > rl) s = -1e30f;
                    Sacc[mt][nt][v] = s;
                }

        // ---- phase A: row max
        #pragma unroll
        for (int mt = 0; mt < 2; mt++)
            #pragma unroll
            for (int half = 0; half < 2; half++) {
                int ri = wm + mt * 16 + half * 8 + gid;
                float mx = -1e30f;
                #pragma unroll
                for (int nt = 0; nt < 8; nt++) {
                    mx = fmaxf(mx, Sacc[mt][nt][half * 2]);
                    mx = fmaxf(mx, Sacc[mt][nt][half * 2 + 1]);
                }
                mx = fmaxf(mx, __shfl_xor_sync(0xffffffffu, mx, 1));
                mx = fmaxf(mx, __shfl_xor_sync(0xffffffffu, mx, 2));
                if (tig == 0) rowred[wc * 128 + ri] = mx;
            }
        __syncthreads();
        if (tid < 128) {
            float tm = fmaxf(rowred[tid], rowred[128 + tid]);
            float mo = row_m[tid];
            float mn = fmaxf(mo, tm);
            row_m[tid] = mn;
            row_r[tid] = __expf(mo - mn);
        }
        __syncthreads();

        // ---- phase B: exp, P write, row sum, O rescale
        #pragma unroll
        for (int mt = 0; mt < 2; mt++)
            #pragma unroll
            for (int half = 0; half < 2; half++) {
                int ri = wm + mt * 16 + half * 8 + gid;
                float m = row_m[ri];
                float rsc = row_r[ri];
                float s = 0.0f;
                #pragma unroll
                for (int nt = 0; nt < 8; nt++) {
                    float p0 = __expf(Sacc[mt][nt][half * 2    ] - m);
                    float p1 = __expf(Sacc[mt][nt][half * 2 + 1] - m);
                    s += p0 + p1;
                    int cl = wn + nt * 8 + tig * 2;
                    *reinterpret_cast<float2*>(&Ps[ri * PPAD + cl]) =
                        make_float2(p0, p1);
                    Oacc[mt][nt][half * 2    ] *= rsc;
                    Oacc[mt][nt][half * 2 + 1] *= rsc;
                }
                s += __shfl_xor_sync(0xffffffffu, s, 1);
                s += __shfl_xor_sync(0xffffffffu, s, 2);
                if (tig == 0) rowred[wc * 128 + ri] = s;
            }
        __syncthreads();
        if (tid < 128)
            row_l[tid] = row_l[tid] * row_r[tid] + rowred[tid] + rowred[128 + tid];
        __syncthreads();

        // ---- O += P @ V, streaming 8 key-chunks of 16
        for (int c = 0; c < 8; c++) {
            if (c + 1 < 8) {
                load_v((13 + c) % 3, c + 1);
                asm volatile("cp.async.commit_group;\n");
                asm volatile("cp.async.wait_group 1;\n");
            } else {
                asm volatile("cp.async.wait_group 0;\n");
            }
            __syncthreads();
            const float* Vs = &KV[((12 + c) % 3) * STG_F];
            #pragma unroll
            for (int ks = 0; ks < 2; ks++) {
                const int kb = ks * 8;
                unsigned af[2][4];
                #pragma unroll
                for (int mt = 0; mt < 2; mt++) {
                    int m0 = wm + mt * 16;
                    int kc = c * 16 + kb + tig;
                    af[mt][0] = f2tf32u(Ps[(m0 + gid    ) * PPAD + kc    ]);
                    af[mt][1] = f2tf32u(Ps[(m0 + gid + 8) * PPAD + kc    ]);
                    af[mt][2] = f2tf32u(Ps[(m0 + gid    ) * PPAD + kc + 4]);
                    af[mt][3] = f2tf32u(Ps[(m0 + gid + 8) * PPAD + kc + 4]);
                }
                #pragma unroll
                for (int nt = 0; nt < 8; nt++) {
                    int n0 = wn + nt * 8;
                    unsigned bf[2];
                    bf[0] = f2tf32u(Vs[(kb + tig    ) * VPAD + n0 + gid]);
                    bf[1] = f2tf32u(Vs[(kb + tig + 4) * VPAD + n0 + gid]);
                    mma_tf32(Oacc[0][nt], af[0], bf);
                    mma_tf32(Oacc[1][nt], af[1], bf);
                }
            }
        }
        __syncthreads();   // protect KV ring before next j's K loads
    }

    // ---- epilogue: O /= l, write ctx[t][h][dv]
    #pragma unroll
    for (int mt = 0; mt < 2; mt++)
        #pragma unroll
        for (int half = 0; half < 2; half++) {
            int ri = wm + mt * 16 + half * 8 + gid;
            float inv = 1.0f / row_l[ri];
            long t = q0 + ri;
            #pragma unroll
            for (int nt = 0; nt < 8; nt++) {
                int cl = wn + nt * 8 + tig * 2;
                float2 v = make_float2(Oacc[mt][nt][half * 2] * inv,
                                       Oacc[mt][nt][half * 2 + 1] * inv);
                *reinterpret_cast<float2*>(&ctx[t * (H_ * DV_) + h * DV_ + cl]) = v;
            }
        }
}

// ------------------------------ RMSNorm ------------------------------------
__global__ void rmsnorm_kernel(const float* __restrict__ x,
                               const float* __restrict__ w,
                               float* __restrict__ y,
                               int L, int ldx, int ldy)
{
    const int row = blockIdx.x, tid = threadIdx.x;
    const float* xr = x + (long)row * ldx;
    float* yr = y + (long)row * ldy;

    __shared__ float red[256];
    float s = 0.0f;
    for (int i = tid; i < L; i += 256) { float v = xr[i]; s += v * v; }
    red[tid] = s; __syncthreads();
    for (int o = 128; o > 0; o >>= 1) {
        if (tid < o) red[tid] += red[tid + o];
        __syncthreads();
    }
    const float scale = rsqrtf(red[0] / (float)L + EPS_);
    for (int i = tid; i < L; i += 256) yr[i] = xr[i] * scale * w[i];
}

// -------------------------------- RoPE -------------------------------------
__global__ void rope_kernel(const float* __restrict__ x, float* __restrict__ o,
                            const float* __restrict__ cosT,
                            const float* __restrict__ sinT,
                            long sxt, int sxh, long sot, int soh)
{
    const int h = blockIdx.x, t = blockIdx.y, i = threadIdx.x;  // i < 64
    const float* xp = x + (long)t * sxt + (long)h * sxh;
    float* op = o + (long)t * sot + (long)h * soh;

    __shared__ float xs[64];
    __shared__ float ys[64];
    xs[i] = xp[i];
    __syncthreads();
    float y = (i < 32) ? xs[2 * i] : xs[2 * (i - 32) + 1];
    ys[i] = y;
    __syncthreads();
    float rot = (i < 32) ? -ys[i + 32] : ys[i - 32];
    op[i] = y * cosT[(long)t * DR_ + i] + rot * sinT[(long)t * DR_ + i];
}

// ------------------------------- launch ------------------------------------
extern "C" void kernel_launch(void* const* d_in, const int* in_sizes, int n_in,
                              void* d_out, int out_size)
{
    const float* hidden = (const float*)d_in[0];
    const float* cosT   = (const float*)d_in[1];
    const float* sinT   = (const float*)d_in[2];
    const float* wq_a   = (const float*)d_in[3];
    const float* q_ln   = (const float*)d_in[4];
    const float* wq_b   = (const float*)d_in[5];
    const float* wkv_a  = (const float*)d_in[6];
    const float* kv_ln  = (const float*)d_in[7];
    const float* wkv_b  = (const float*)d_in[8];
    const float* wo     = (const float*)d_in[9];
    float* out = (float*)d_out;

    static float *qa = nullptr, *q = nullptr, *ckv = nullptr, *cn = nullptr,
                 *kv = nullptr, *kr = nullptr, *ctx = nullptr;
    if (!qa) {
        cudaGetSymbolAddress((void**)&qa,  g_qa);
        cudaGetSymbolAddress((void**)&q,   g_q);
        cudaGetSymbolAddress((void**)&ckv, g_ckv);
        cudaGetSymbolAddress((void**)&cn,  g_cn);
        cudaGetSymbolAddress((void**)&kv,  g_kv);
        cudaGetSymbolAddress((void**)&kr,  g_kr);
        cudaGetSymbolAddress((void**)&ctx, g_ctx);
        cudaFuncSetAttribute(tgemm_kernel,
                             cudaFuncAttributeMaxDynamicSharedMemorySize, SMEM_BYTES);
        cudaFuncSetAttribute(fused_attn_kernel,
                             cudaFuncAttributeMaxDynamicSharedMemorySize, FUSED_SMEM);
    }

    const dim3 blk(256);

    // 1) q_a = hidden @ wq_a                       [2048 x 1536]
    tgemm_kernel<<<dim3(12, 16, 1), blk, SMEM_BYTES>>>(
        hidden, wq_a, qa, T_, QL_, HIDDEN_, HIDDEN_, QL_, QL_);

    // 2) rmsnorm(q_a) in place
    rmsnorm_kernel<<<T_, 256>>>(qa, q_ln, qa, QL_, QL_, QL_);

    // 3) q = q_a_n @ wq_b                          [2048 x 6144]
    tgemm_kernel<<<dim3(48, 16, 1), blk, SMEM_BYTES>>>(
        qa, wq_b, q, T_, H_ * DQK_, QL_, QL_, H_ * DQK_, H_ * DQK_);

    // 4) ckv = hidden @ wkv_a                      [2048 x 576]
    tgemm_kernel<<<dim3(5, 16, 1), blk, SMEM_BYTES>>>(
        hidden, wkv_a, ckv, T_, KVL_ + DR_, HIDDEN_,
        HIDDEN_, KVL_ + DR_, KVL_ + DR_);

    // 5) cn = rmsnorm(ckv[:, :512])
    rmsnorm_kernel<<<T_, 256>>>(ckv, kv_ln, cn, KVL_, KVL_ + DR_, KVL_);

    // 6) kv = cn @ wkv_b                           [2048 x 8192]
    tgemm_kernel<<<dim3(64, 16, 1), blk, SMEM_BYTES>>>(
        cn, wkv_b, kv, T_, H_ * (DN_ + DV_), KVL_,
        KVL_, H_ * (DN_ + DV_), H_ * (DN_ + DV_));

    // 7) RoPE on q_pe (in place)
    rope_kernel<<<dim3(H_, T_), 64>>>(q + DN_, q + DN_, cosT, sinT,
                                      H_ * DQK_, DQK_, H_ * DQK_, DQK_);

    // 8) RoPE on k_pe -> kr
    rope_kernel<<<dim3(1, T_), 64>>>(ckv + KVL_, kr, cosT, sinT,
                                     KVL_ + DR_, 0, DR_, 0);

    // 9) fused attention: ctx = softmax(QK^T) @ V   per (qtile, head)
    fused_attn_kernel<<<dim3(16, H_, 1), blk, FUSED_SMEM>>>(q, kv, kr, ctx);

    // 10) out = ctx @ wo                           [2048 x 5120]
    tgemm_kernel<<<dim3(40, 16, 1), blk, SMEM_BYTES>>>(
        ctx, wo, out, T_, HIDDEN_, H_ * DV_,
        H_ * DV_, HIDDEN_, HIDDEN_);
}

// round 6
// speedup vs baseline: 7.2172x; 1.0270x over previous
#include <cuda_runtime.h>
#include <math.h>

// ---------------------------------------------------------------------------
// DeepSeek V2 MLA attention prefill — TF32 mma.sync GEMMs, 4-stage cp.async,
// all operands pre-rounded to tf32 in gmem (no cvt in mainloops), fused
// flash attention. T=2048, H=32, HIDDEN=5120, QL=1536, KVL=512.
// ---------------------------------------------------------------------------

namespace {
constexpr int T_      = 2048;
constexpr int H_      = 32;
constexpr int HIDDEN_ = 5120;
constexpr int QL_     = 1536;
constexpr int KVL_    = 512;
constexpr int DN_     = 128;
constexpr int DR_     = 64;
constexpr int DQK_    = 192;
constexpr int DV_     = 128;
constexpr int CKVP_   = 640;   // ckv scratch width (multiple of 128)
constexpr float EPS_  = 1e-6f;
constexpr float SCALING_ = 0.07216878364870323f;  // 192^-0.5
constexpr int SMEM_BYTES = 4 * (2560 + 2560) * 4;   // 80 KB (dense GEMM)

// fused attention smem layout (floats)
constexpr int QPAD  = 204;
constexpr int KPAD  = 20;
constexpr int VPAD  = 136;
constexpr int PPAD  = 132;
constexpr int QS_F  = 128 * QPAD;
constexpr int STG_F = 2560;
constexpr int PS_F  = 128 * PPAD;
constexpr int FUSED_F = QS_F + 3 * STG_F + PS_F + 3 * 128 + 256;
constexpr int FUSED_SMEM = FUSED_F * 4;
}

// ------------------------- scratch (static device) -------------------------
__device__ float g_hid[(long)T_ * HIDDEN_];          // tf32-rounded hidden
__device__ float g_qa [(long)T_ * QL_];
__device__ float g_q  [(long)T_ * H_ * DQK_];
__device__ float g_ckv[(long)T_ * CKVP_];
__device__ float g_cn [(long)T_ * KVL_];
__device__ float g_kv [(long)T_ * H_ * (DN_ + DV_)];
__device__ float g_kr [(long)T_ * DR_];
__device__ float g_ctx[(long)T_ * H_ * DV_];
// tf32-rounded weights (same layout as inputs; wkv_a padded to 640 cols)
__device__ float g_wqa [(long)HIDDEN_ * QL_];
__device__ float g_wqb [(long)QL_ * (H_ * DQK_)];
__device__ float g_wkva[(long)HIDDEN_ * CKVP_];
__device__ float g_wkvb[(long)KVL_ * (H_ * (DN_ + DV_))];
__device__ float g_wo  [(long)(H_ * DV_) * HIDDEN_];

// ------------------------------ helpers ------------------------------------
__device__ __forceinline__ unsigned f2tf32u(float x) {
    unsigned u;
    asm("cvt.rna.tf32.f32 %0, %1;" : "=r"(u) : "f"(x));
    return u;
}
__device__ __forceinline__ float f2tf32f(float x) {
    return __uint_as_float(f2tf32u(x));
}

__device__ __forceinline__ void mma_tf32(float* d, const unsigned* a, const unsigned* b) {
    asm volatile(
        "mma.sync.aligned.m16n8k8.row.col.f32.tf32.tf32.f32 "
        "{%0,%1,%2,%3}, {%4,%5,%6,%7}, {%8,%9}, {%0,%1,%2,%3};"
        : "+f"(d[0]), "+f"(d[1]), "+f"(d[2]), "+f"(d[3])
        : "r"(a[0]), "r"(a[1]), "r"(a[2]), "r"(a[3]),
          "r"(b[0]), "r"(b[1]));
}

__device__ __forceinline__ unsigned smem_u32(const void* p) {
    return (unsigned)__cvta_generic_to_shared(p);
}
__device__ __forceinline__ void cp16(unsigned dst, const void* src) {
    asm volatile("cp.async.cg.shared.global [%0], [%1], 16;\n" :: "r"(dst), "l"(src));
}
__device__ __forceinline__ unsigned ldu(const float* p) {
    return __float_as_uint(*p);
}

// ------------------------------- TF32 GEMM ---------------------------------
// C[M,N] = A @ B  (B is KxN row-major), operands pre-rounded to tf32.
// Tile 128x128x16, 4-stage cp.async. All dims multiples of tile sizes.
// RND: round outputs to tf32 (for buffers feeding further tf32 mma).
template<bool RND>
__global__ __launch_bounds__(256, 2)
void tgemm_kernel(const float* __restrict__ A,
                  const float* __restrict__ B,
                  float* __restrict__ C,
                  int M, int N, int K,
                  int lda, int ldb, int ldc)
{
    constexpr int BM = 128, BK = 16, S = 4;
    constexpr int APAD = 20;
    constexpr int BPAD_KN = 136;
    constexpr int ASTAGE = BM * APAD;
    constexpr int BSTAGE = 2560;

    const int bx = blockIdx.x, by = blockIdx.y;

    extern __shared__ float smem[];
    float* As = smem;
    float* Bs = smem + S * ASTAGE;

    const int tid  = threadIdx.x;
    const int lane = tid & 31;
    const int warp = tid >> 5;
    const int gid  = lane >> 2;
    const int tig  = lane & 3;
    const int wr   = warp & 3;
    const int wc   = warp >> 2;
    const int rowBase = by * BM, colBase = bx * 128;
    const int wm = wr * 32, wn = wc * 64;

    const int tiles = K / BK;

    auto load_tile = [&](int st, int kt) {
        const int k0 = kt * BK;
        #pragma unroll
        for (int i = 0; i < 2; i++) {
            int c = tid + i * 256;
            int r = c >> 2, kc = (c & 3) * 4;
            cp16(smem_u32(&As[st * ASTAGE + r * APAD + kc]),
                 &A[(long)(rowBase + r) * lda + (k0 + kc)]);
        }
        #pragma unroll
        for (int i = 0; i < 2; i++) {
            int c = tid + i * 256;
            int r = c >> 5, nc = (c & 31) * 4;
            cp16(smem_u32(&Bs[st * BSTAGE + r * BPAD_KN + nc]),
                 &B[(long)(k0 + r) * ldb + colBase + nc]);
        }
    };

    #pragma unroll
    for (int s = 0; s < S - 1; s++) {
        if (s < tiles) load_tile(s, s);
        asm volatile("cp.async.commit_group;\n");
    }

    float acc[2][8][4];
    #pragma unroll
    for (int i = 0; i < 2; i++)
        #pragma unroll
        for (int j = 0; j < 8; j++)
            #pragma unroll
            for (int v = 0; v < 4; v++) acc[i][j][v] = 0.0f;

    for (int t = 0; t < tiles; t++) {
        asm volatile("cp.async.wait_group %0;\n" :: "n"(S - 2));
        __syncthreads();

        int tn = t + S - 1;
        if (tn < tiles) load_tile(tn % S, tn);
        asm volatile("cp.async.commit_group;\n");

        const int st = t % S;
        const float* Asb = &As[st * ASTAGE];
        const float* Bsb = &Bs[st * BSTAGE];

        #pragma unroll
        for (int ks = 0; ks < 2; ks++) {
            const int kb = ks * 8;
            unsigned af[2][4];
            #pragma unroll
            for (int mt = 0; mt < 2; mt++) {
                int m0 = wm + mt * 16;
                af[mt][0] = ldu(&Asb[(m0 + gid    ) * APAD + kb + tig    ]);
                af[mt][1] = ldu(&Asb[(m0 + gid + 8) * APAD + kb + tig    ]);
                af[mt][2] = ldu(&Asb[(m0 + gid    ) * APAD + kb + tig + 4]);
                af[mt][3] = ldu(&Asb[(m0 + gid + 8) * APAD + kb + tig + 4]);
            }
            #pragma unroll
            for (int nt = 0; nt < 8; nt++) {
                int n0 = wn + nt * 8;
                unsigned bf[2];
                bf[0] = ldu(&Bsb[(kb + tig    ) * BPAD_KN + n0 + gid]);
                bf[1] = ldu(&Bsb[(kb + tig + 4) * BPAD_KN + n0 + gid]);
                mma_tf32(acc[0][nt], af[0], bf);
                mma_tf32(acc[1][nt], af[1], bf);
            }
        }
    }

    #pragma unroll
    for (int mt = 0; mt < 2; mt++) {
        #pragma unroll
        for (int nt = 0; nt < 8; nt++) {
            int gc = colBase + wn + nt * 8 + tig * 2;
            #pragma unroll
            for (int half = 0; half < 2; half++) {
                int gr = rowBase + wm + mt * 16 + gid + half * 8;
                float x0 = acc[mt][nt][half * 2];
                float x1 = acc[mt][nt][half * 2 + 1];
                if (RND) { x0 = f2tf32f(x0); x1 = f2tf32f(x1); }
                *reinterpret_cast<float2*>(&C[(long)gr * ldc + gc]) =
                    make_float2(x0, x1);
            }
        }
    }
}

// --------------------- fused flash attention kernel ------------------------
// Inputs q/kv/kr pre-rounded to tf32; ctx output rounded (feeds out-GEMM).
__global__ __launch_bounds__(256, 1)
void fused_attn_kernel(const float* __restrict__ q,
                       const float* __restrict__ kv,
                       const float* __restrict__ kr,
                       float* __restrict__ ctx)
{
    extern __shared__ float sm[];
    float* Qs     = sm;
    float* KV     = sm + QS_F;
    float* Ps     = sm + QS_F + 3 * STG_F;
    float* row_m  = Ps + PS_F;
    float* row_l  = row_m + 128;
    float* row_r  = row_l + 128;
    float* rowred = row_r + 128;

    const int qt = 15 - blockIdx.x;
    const int h  = blockIdx.y;
    const long q0 = (long)qt * 128;

    const int tid  = threadIdx.x;
    const int lane = tid & 31;
    const int warp = tid >> 5;
    const int gid  = lane >> 2;
    const int tig  = lane & 3;
    const int wr   = warp & 3;
    const int wc   = warp >> 2;
    const int wm = wr * 32, wn = wc * 64;
    const int KVROW = H_ * (DN_ + DV_);

    if (tid < 128) { row_m[tid] = -1e30f; row_l[tid] = 0.0f; }

    const float* Qbase = q + q0 * (H_ * DQK_) + h * DQK_;
    #pragma unroll
    for (int i = 0; i < 24; i++) {
        int e = tid + i * 256;
        int r = e / 48;
        int fc = (e % 48) * 4;
        cp16(smem_u32(&Qs[r * QPAD + fc]), Qbase + (long)r * (H_ * DQK_) + fc);
    }
    asm volatile("cp.async.commit_group;\n");

    float Oacc[2][8][4];
    #pragma unroll
    for (int i = 0; i < 2; i++)
        #pragma unroll
        for (int j = 0; j < 8; j++)
            #pragma unroll
            for (int v = 0; v < 4; v++) Oacc[i][j][v] = 0.0f;

    for (int j = 0; j <= qt; j++) {
        const long key0 = (long)j * 128;
        const bool diag = (j == qt);

        auto load_k = [&](int st, int c) {
            const int d0 = c * 16;
            float* dst = &KV[st * STG_F];
            #pragma unroll
            for (int i = 0; i < 2; i++) {
                int e = tid + i * 256;
                int r = e >> 2;
                int fc = (e & 3) * 4;
                const float* src = (d0 < DN_)
                    ? kv + (key0 + r) * (long)KVROW + h * (DN_ + DV_) + d0 + fc
                    : kr + (key0 + r) * (long)DR_ + (d0 - DN_) + fc;
                cp16(smem_u32(dst + r * KPAD + fc), src);
            }
        };
        auto load_v = [&](int st, int c) {
            float* dst = &KV[st * STG_F];
            #pragma unroll
            for (int i = 0; i < 2; i++) {
                int e = tid + i * 256;
                int r = e >> 5;
                int fc = (e & 31) * 4;
                const float* src = kv + (key0 + c * 16 + r) * (long)KVROW
                                   + h * (DN_ + DV_) + DN_ + fc;
                cp16(smem_u32(dst + r * VPAD + fc), src);
            }
        };

        float Sacc[2][8][4];
        #pragma unroll
        for (int i = 0; i < 2; i++)
            #pragma unroll
            for (int jj = 0; jj < 8; jj++)
                #pragma unroll
                for (int v = 0; v < 4; v++) Sacc[i][jj][v] = 0.0f;

        load_k(0, 0);
        asm volatile("cp.async.commit_group;\n");
        for (int c = 0; c < 12; c++) {
            if (c + 1 < 12) {
                load_k((c + 1) % 3, c + 1);
                asm volatile("cp.async.commit_group;\n");
                asm volatile("cp.async.wait_group 1;\n");
            } else {
                asm volatile("cp.async.wait_group 0;\n");
            }
            __syncthreads();
            const float* Ks = &KV[(c % 3) * STG_F];
            const int dbase = c * 16;
            #pragma unroll
            for (int ks = 0; ks < 2; ks++) {
                const int kb = ks * 8;
                unsigned af[2][4];
                #pragma unroll
                for (int mt = 0; mt < 2; mt++) {
                    int m0 = wm + mt * 16;
                    af[mt][0] = ldu(&Qs[(m0 + gid    ) * QPAD + dbase + kb + tig    ]);
                    af[mt][1] = ldu(&Qs[(m0 + gid + 8) * QPAD + dbase + kb + tig    ]);
                    af[mt][2] = ldu(&Qs[(m0 + gid    ) * QPAD + dbase + kb + tig + 4]);
                    af[mt][3] = ldu(&Qs[(m0 + gid + 8) * QPAD + dbase + kb + tig + 4]);
                }
                #pragma unroll
                for (int nt = 0; nt < 8; nt++) {
                    int n0 = wn + nt * 8;
                    unsigned bf[2];
                    bf[0] = ldu(&Ks[(n0 + gid) * KPAD + kb + tig    ]);
                    bf[1] = ldu(&Ks[(n0 + gid) * KPAD + kb + tig + 4]);
                    mma_tf32(Sacc[0][nt], af[0], bf);
                    mma_tf32(Sacc[1][nt], af[1], bf);
                }
            }
        }

        load_v(0, 0);
        asm volatile("cp.async.commit_group;\n");

        #pragma unroll
        for (int mt = 0; mt < 2; mt++)
            #pragma unroll
            for (int nt = 0; nt < 8; nt++)
                #pragma unroll
                for (int v = 0; v < 4; v++) {
                    int rl = wm + mt * 16 + (v >> 1) * 8 + gid;
                    int cl = wn + nt * 8 + tig * 2 + (v & 1);
                    float s = Sacc[mt][nt][v] * SCALING_;
                    if (diag && cl > rl) s = -1e30f;
                    Sacc[mt][nt][v] = s;
                }

        #pragma unroll
        for (int mt = 0; mt < 2; mt++)
            #pragma unroll
            for (int half = 0; half < 2; half++) {
                int ri = wm + mt * 16 + half * 8 + gid;
                float mx = -1e30f;
                #pragma unroll
                for (int nt = 0; nt < 8; nt++) {
                    mx = fmaxf(mx, Sacc[mt][nt][half * 2]);
                    mx = fmaxf(mx, Sacc[mt][nt][half * 2 + 1]);
                }
                mx = fmaxf(mx, __shfl_xor_sync(0xffffffffu, mx, 1));
                mx = fmaxf(mx, __shfl_xor_sync(0xffffffffu, mx, 2));
                if (tig == 0) rowred[wc * 128 + ri] = mx;
            }
        __syncthreads();
        if (tid < 128) {
            float tm = fmaxf(rowred[tid], rowred[128 + tid]);
            float mo = row_m[tid];
            float mn = fmaxf(mo, tm);
            row_m[tid] = mn;
            row_r[tid] = __expf(mo - mn);
        }
        __syncthreads();

        #pragma unroll
        for (int mt = 0; mt < 2; mt++)
            #pragma unroll
            for (int half = 0; half < 2; half++) {
                int ri = wm + mt * 16 + half * 8 + gid;
                float m = row_m[ri];
                float rsc = row_r[ri];
                float s = 0.0f;
                #pragma unroll
                for (int nt = 0; nt < 8; nt++) {
                    float p0 = f2tf32f(__expf(Sacc[mt][nt][half * 2    ] - m));
                    float p1 = f2tf32f(__expf(Sacc[mt][nt][half * 2 + 1] - m));
                    s += p0 + p1;
                    int cl = wn + nt * 8 + tig * 2;
                    *reinterpret_cast<float2*>(&Ps[ri * PPAD + cl]) =
                        make_float2(p0, p1);
                    Oacc[mt][nt][half * 2    ] *= rsc;
                    Oacc[mt][nt][half * 2 + 1] *= rsc;
                }
                s += __shfl_xor_sync(0xffffffffu, s, 1);
                s += __shfl_xor_sync(0xffffffffu, s, 2);
                if (tig == 0) rowred[wc * 128 + ri] = s;
            }
        __syncthreads();
        if (tid < 128)
            row_l[tid] = row_l[tid] * row_r[tid] + rowred[tid] + rowred[128 + tid];
        __syncthreads();

        for (int c = 0; c < 8; c++) {
            if (c + 1 < 8) {
                load_v((13 + c) % 3, c + 1);
                asm volatile("cp.async.commit_group;\n");
                asm volatile("cp.async.wait_group 1;\n");
            } else {
                asm volatile("cp.async.wait_group 0;\n");
            }
            __syncthreads();
            const float* Vs = &KV[((12 + c) % 3) * STG_F];
            #pragma unroll
            for (int ks = 0; ks < 2; ks++) {
                const int kb = ks * 8;
                unsigned af[2][4];
                #pragma unroll
                for (int mt = 0; mt < 2; mt++) {
                    int m0 = wm + mt * 16;
                    int kc = c * 16 + kb + tig;
                    af[mt][0] = ldu(&Ps[(m0 + gid    ) * PPAD + kc    ]);
                    af[mt][1] = ldu(&Ps[(m0 + gid + 8) * PPAD + kc    ]);
                    af[mt][2] = ldu(&Ps[(m0 + gid    ) * PPAD + kc + 4]);
                    af[mt][3] = ldu(&Ps[(m0 + gid + 8) * PPAD + kc + 4]);
                }
                #pragma unroll
                for (int nt = 0; nt < 8; nt++) {
                    int n0 = wn + nt * 8;
                    unsigned bf[2];
                    bf[0] = ldu(&Vs[(kb + tig    ) * VPAD + n0 + gid]);
                    bf[1] = ldu(&Vs[(kb + tig + 4) * VPAD + n0 + gid]);
                    mma_tf32(Oacc[0][nt], af[0], bf);
                    mma_tf32(Oacc[1][nt], af[1], bf);
                }
            }
        }
        __syncthreads();
    }

    // epilogue: O /= l, tf32-rounded (feeds out-GEMM)
    #pragma unroll
    for (int mt = 0; mt < 2; mt++)
        #pragma unroll
        for (int half = 0; half < 2; half++) {
            int ri = wm + mt * 16 + half * 8 + gid;
            float inv = 1.0f / row_l[ri];
            long t = q0 + ri;
            #pragma unroll
            for (int nt = 0; nt < 8; nt++) {
                int cl = wn + nt * 8 + tig * 2;
                float2 v = make_float2(f2tf32f(Oacc[mt][nt][half * 2] * inv),
                                       f2tf32f(Oacc[mt][nt][half * 2 + 1] * inv));
                *reinterpret_cast<float2*>(&ctx[t * (H_ * DV_) + h * DV_ + cl]) = v;
            }
        }
}

// ------------------------------ prep kernels --------------------------------
__global__ void round_kernel(const float* __restrict__ in,
                             float* __restrict__ out, long n)
{
    long i = ((long)blockIdx.x * blockDim.x + threadIdx.x) * 4;
    if (i < n) {
        float4 v = *reinterpret_cast<const float4*>(in + i);
        *reinterpret_cast<float4*>(out + i) =
            make_float4(f2tf32f(v.x), f2tf32f(v.y), f2tf32f(v.z), f2tf32f(v.w));
    }
}

// in [R][Cin] -> out [R][Cpad], zero-pad, rounded
__global__ void pad_round_kernel(const float* __restrict__ in,
                                 float* __restrict__ out, int R, int Cin, int Cpad)
{
    long i = (long)blockIdx.x * blockDim.x + threadIdx.x;
    long n = (long)R * Cpad;
    if (i < n) {
        int r = (int)(i / Cpad), c = (int)(i % Cpad);
        out[i] = (c < Cin) ? f2tf32f(in[(long)r * Cin + c]) : 0.0f;
    }
}

// ------------------------------ RMSNorm ------------------------------------
// output tf32-rounded (feeds tf32 GEMM A operand)
__global__ void rmsnorm_kernel(const float* __restrict__ x,
                               const float* __restrict__ w,
                               float* __restrict__ y,
                               int L, int ldx, int ldy)
{
    const int row = blockIdx.x, tid = threadIdx.x;
    const float* xr = x + (long)row * ldx;
    float* yr = y + (long)row * ldy;

    __shared__ float red[256];
    float s = 0.0f;
    for (int i = tid; i < L; i += 256) { float v = xr[i]; s += v * v; }
    red[tid] = s; __syncthreads();
    for (int o = 128; o > 0; o >>= 1) {
        if (tid < o) red[tid] += red[tid + o];
        __syncthreads();
    }
    const float scale = rsqrtf(red[0] / (float)L + EPS_);
    for (int i = tid; i < L; i += 256) yr[i] = f2tf32f(xr[i] * scale * w[i]);
}

// -------------------------------- RoPE -------------------------------------
// output tf32-rounded
__global__ void rope_kernel(const float* __restrict__ x, float* __restrict__ o,
                            const float* __restrict__ cosT,
                            const float* __restrict__ sinT,
                            long sxt, int sxh, long sot, int soh)
{
    const int h = blockIdx.x, t = blockIdx.y, i = threadIdx.x;  // i < 64
    const float* xp = x + (long)t * sxt + (long)h * sxh;
    float* op = o + (long)t * sot + (long)h * soh;

    __shared__ float xs[64];
    __shared__ float ys[64];
    xs[i] = xp[i];
    __syncthreads();
    float y = (i < 32) ? xs[2 * i] : xs[2 * (i - 32) + 1];
    ys[i] = y;
    __syncthreads();
    float rot = (i < 32) ? -ys[i + 32] : ys[i - 32];
    op[i] = f2tf32f(y * cosT[(long)t * DR_ + i] + rot * sinT[(long)t * DR_ + i]);
}

// ------------------------------- launch ------------------------------------
extern "C" void kernel_launch(void* const* d_in, const int* in_sizes, int n_in,
                              void* d_out, int out_size)
{
    const float* hidden = (const float*)d_in[0];
    const float* cosT   = (const float*)d_in[1];
    const float* sinT   = (const float*)d_in[2];
    const float* wq_a   = (const float*)d_in[3];
    const float* q_ln   = (const float*)d_in[4];
    const float* wq_b   = (const float*)d_in[5];
    const float* wkv_a  = (const float*)d_in[6];
    const float* kv_ln  = (const float*)d_in[7];
    const float* wkv_b  = (const float*)d_in[8];
    const float* wo     = (const float*)d_in[9];
    float* out = (float*)d_out;

    static float *hid = nullptr, *qa = nullptr, *q = nullptr, *ckv = nullptr,
                 *cn = nullptr, *kv = nullptr, *kr = nullptr, *ctx = nullptr,
                 *wqa = nullptr, *wqb = nullptr, *wkva = nullptr,
                 *wkvb = nullptr, *woR = nullptr;
    if (!qa) {
        cudaGetSymbolAddress((void**)&hid,  g_hid);
        cudaGetSymbolAddress((void**)&qa,   g_qa);
        cudaGetSymbolAddress((void**)&q,    g_q);
        cudaGetSymbolAddress((void**)&ckv,  g_ckv);
        cudaGetSymbolAddress((void**)&cn,   g_cn);
        cudaGetSymbolAddress((void**)&kv,   g_kv);
        cudaGetSymbolAddress((void**)&kr,   g_kr);
        cudaGetSymbolAddress((void**)&ctx,  g_ctx);
        cudaGetSymbolAddress((void**)&wqa,  g_wqa);
        cudaGetSymbolAddress((void**)&wqb,  g_wqb);
        cudaGetSymbolAddress((void**)&wkva, g_wkva);
        cudaGetSymbolAddress((void**)&wkvb, g_wkvb);
        cudaGetSymbolAddress((void**)&woR,  g_wo);
        cudaFuncSetAttribute(tgemm_kernel<false>,
                             cudaFuncAttributeMaxDynamicSharedMemorySize, SMEM_BYTES);
        cudaFuncSetAttribute(tgemm_kernel<true>,
                             cudaFuncAttributeMaxDynamicSharedMemorySize, SMEM_BYTES);
        cudaFuncSetAttribute(fused_attn_kernel,
                             cudaFuncAttributeMaxDynamicSharedMemorySize, FUSED_SMEM);
    }

    const dim3 blk(256);

    // 0) prep: tf32-round hidden + weights into scratch (wkv_a padded to 640)
    round_kernel<<<(int)(((long)T_ * HIDDEN_ / 4 + 255) / 256), 256>>>(
        hidden, hid, (long)T_ * HIDDEN_);
    round_kernel<<<(int)(((long)HIDDEN_ * QL_ / 4 + 255) / 256), 256>>>(
        wq_a, wqa, (long)HIDDEN_ * QL_);
    round_kernel<<<(int)(((long)QL_ * H_ * DQK_ / 4 + 255) / 256), 256>>>(
        wq_b, wqb, (long)QL_ * H_ * DQK_);
    pad_round_kernel<<<(int)(((long)HIDDEN_ * CKVP_ + 255) / 256), 256>>>(
        wkv_a, wkva, HIDDEN_, KVL_ + DR_, CKVP_);
    round_kernel<<<(int)(((long)KVL_ * H_ * (DN_ + DV_) / 4 + 255) / 256), 256>>>(
        wkv_b, wkvb, (long)KVL_ * H_ * (DN_ + DV_));
    round_kernel<<<(int)(((long)(H_ * DV_) * HIDDEN_ / 4 + 255) / 256), 256>>>(
        wo, woR, (long)(H_ * DV_) * HIDDEN_);

    // 1) q_a = hid @ wq_a           [2048 x 1536]
    tgemm_kernel<false><<<dim3(QL_ / 128, 16), blk, SMEM_BYTES>>>(
        hid, wqa, qa, T_, QL_, HIDDEN_, HIDDEN_, QL_, QL_);
    // 2) rmsnorm(q_a) in place (rounded)
    rmsnorm_kernel<<<T_, 256>>>(qa, q_ln, qa, QL_, QL_, QL_);
    // 3) q = q_a_n @ wq_b           [2048 x 6144] (rounded)
    tgemm_kernel<true><<<dim3(H_ * DQK_ / 128, 16), blk, SMEM_BYTES>>>(
        qa, wqb, q, T_, H_ * DQK_, QL_, QL_, H_ * DQK_, H_ * DQK_);
    // 4) ckv = hid @ wkv_a          [2048 x 640]
    tgemm_kernel<false><<<dim3(CKVP_ / 128, 16), blk, SMEM_BYTES>>>(
        hid, wkva, ckv, T_, CKVP_, HIDDEN_, HIDDEN_, CKVP_, CKVP_);
    // 5) cn = rmsnorm(ckv[:, :512]) (rounded)
    rmsnorm_kernel<<<T_, 256>>>(ckv, kv_ln, cn, KVL_, CKVP_, KVL_);
    // 6) kv = cn @ wkv_b            [2048 x 8192] (rounded)
    tgemm_kernel<true><<<dim3(H_ * (DN_ + DV_) / 128, 16), blk, SMEM_BYTES>>>(
        cn, wkvb, kv, T_, H_ * (DN_ + DV_), KVL_,
        KVL_, H_ * (DN_ + DV_), H_ * (DN_ + DV_));
    // 7) RoPE on q_pe (in place, rounded)
    rope_kernel<<<dim3(H_, T_), 64>>>(q + DN_, q + DN_, cosT, sinT,
                                      H_ * DQK_, DQK_, H_ * DQK_, DQK_);
    // 8) RoPE on k_pe -> kr (rounded)
    rope_kernel<<<dim3(1, T_), 64>>>(ckv + KVL_, kr, cosT, sinT,
                                     CKVP_, 0, DR_, 0);
    // 9) fused attention: ctx = softmax(QK^T) @ V (ctx rounded)
    fused_attn_kernel<<<dim3(16, H_), blk, FUSED_SMEM>>>(q, kv, kr, ctx);
    // 10) out = ctx @ wo            [2048 x 5120] (NOT rounded)
    tgemm_kernel<false><<<dim3(HIDDEN_ / 128, 16), blk, SMEM_BYTES>>>(
        ctx, woR, out, T_, HIDDEN_, H_ * DV_, H_ * DV_, HIDDEN_, HIDDEN_);
}

// round 7
// speedup vs baseline: 12.1334x; 1.6812x over previous
#include <cuda_runtime.h>
#include <cuda_fp16.h>
#include <math.h>

// ---------------------------------------------------------------------------
// DeepSeek V2 MLA attention prefill.
//  - Dense GEMMs: fp16 mma.sync m16n8k16 + ldmatrix, 4-stage cp.async.
//  - Attention: fused flash kernel, tf32 mma (fp32 smem), outputs half ctx.
// ---------------------------------------------------------------------------

namespace {
constexpr int T_      = 2048;
constexpr int H_      = 32;
constexpr int HIDDEN_ = 5120;
constexpr int QL_     = 1536;
constexpr int KVL_    = 512;
constexpr int DN_     = 128;
constexpr int DR_     = 64;
constexpr int DQK_    = 192;
constexpr int DV_     = 128;
constexpr int CKVP_   = 640;   // ckv scratch width (multiple of 128)
constexpr float EPS_  = 1e-6f;
constexpr float SCALING_ = 0.07216878364870323f;  // 192^-0.5

// fp16 GEMM smem (halves)
constexpr int APAD_H = 40;                  // A row stride, conflict-free ldsm
constexpr int BPAD_H = 136;                 // B row stride, conflict-free ldsm.t
constexpr int ASTG_H = 128 * APAD_H;        // 5120
constexpr int BSTG_H = 32 * BPAD_H;         // 4352
constexpr int STG_H  = ASTG_H + BSTG_H;     // 9472 halves = 18944 B
constexpr int GSMEM_BYTES = 4 * STG_H * 2;  // 75776 B

// fused attention smem layout (floats)
constexpr int QPAD  = 204;
constexpr int KPAD  = 20;
constexpr int VPAD  = 136;
constexpr int PPAD  = 132;
constexpr int QS_F  = 128 * QPAD;
constexpr int STG_F = 2560;
constexpr int PS_F  = 128 * PPAD;
constexpr int FUSED_F = QS_F + 3 * STG_F + PS_F + 3 * 128 + 256;
constexpr int FUSED_SMEM = FUSED_F * 4;
}

// ------------------------- scratch (static device) -------------------------
__device__ __half g_hidH[(long)T_ * HIDDEN_];
__device__ float  g_qa32[(long)T_ * QL_];
__device__ __half g_qa16[(long)T_ * QL_];
__device__ float  g_q  [(long)T_ * H_ * DQK_];
__device__ float  g_ckv[(long)T_ * CKVP_];
__device__ __half g_cn16[(long)T_ * KVL_];
__device__ float  g_kv [(long)T_ * H_ * (DN_ + DV_)];
__device__ float  g_kr [(long)T_ * DR_];
__device__ __half g_ctx16[(long)T_ * H_ * DV_];
// fp16 weights (same layout as inputs; wkv_a padded to 640 cols)
__device__ __half g_wqa [(long)HIDDEN_ * QL_];
__device__ __half g_wqb [(long)QL_ * (H_ * DQK_)];
__device__ __half g_wkva[(long)HIDDEN_ * CKVP_];
__device__ __half g_wkvb[(long)KVL_ * (H_ * (DN_ + DV_))];
__device__ __half g_wo  [(long)(H_ * DV_) * HIDDEN_];

// ------------------------------ helpers ------------------------------------
__device__ __forceinline__ unsigned f2tf32u(float x) {
    unsigned u;
    asm("cvt.rna.tf32.f32 %0, %1;" : "=r"(u) : "f"(x));
    return u;
}
__device__ __forceinline__ float f2tf32f(float x) {
    return __uint_as_float(f2tf32u(x));
}

__device__ __forceinline__ void mma_tf32(float* d, const unsigned* a, const unsigned* b) {
    asm volatile(
        "mma.sync.aligned.m16n8k8.row.col.f32.tf32.tf32.f32 "
        "{%0,%1,%2,%3}, {%4,%5,%6,%7}, {%8,%9}, {%0,%1,%2,%3};"
        : "+f"(d[0]), "+f"(d[1]), "+f"(d[2]), "+f"(d[3])
        : "r"(a[0]), "r"(a[1]), "r"(a[2]), "r"(a[3]),
          "r"(b[0]), "r"(b[1]));
}

__device__ __forceinline__ void mma_f16(float* d, const unsigned* a, const unsigned* b) {
    asm volatile(
        "mma.sync.aligned.m16n8k16.row.col.f32.f16.f16.f32 "
        "{%0,%1,%2,%3}, {%4,%5,%6,%7}, {%8,%9}, {%0,%1,%2,%3};"
        : "+f"(d[0]), "+f"(d[1]), "+f"(d[2]), "+f"(d[3])
        : "r"(a[0]), "r"(a[1]), "r"(a[2]), "r"(a[3]),
          "r"(b[0]), "r"(b[1]));
}

__device__ __forceinline__ void ldsm_x4(unsigned* r, unsigned addr) {
    asm volatile("ldmatrix.sync.aligned.m8n8.x4.shared.b16 {%0,%1,%2,%3}, [%4];"
                 : "=r"(r[0]), "=r"(r[1]), "=r"(r[2]), "=r"(r[3]) : "r"(addr));
}
__device__ __forceinline__ void ldsm_x4t(unsigned* r, unsigned addr) {
    asm volatile("ldmatrix.sync.aligned.m8n8.x4.trans.shared.b16 {%0,%1,%2,%3}, [%4];"
                 : "=r"(r[0]), "=r"(r[1]), "=r"(r[2]), "=r"(r[3]) : "r"(addr));
}

__device__ __forceinline__ unsigned smem_u32(const void* p) {
    return (unsigned)__cvta_generic_to_shared(p);
}
__device__ __forceinline__ void cp16(unsigned dst, const void* src) {
    asm volatile("cp.async.cg.shared.global [%0], [%1], 16;\n" :: "r"(dst), "l"(src));
}
__device__ __forceinline__ unsigned ldu(const float* p) {
    return __float_as_uint(*p);
}

// ------------------------------- FP16 GEMM ---------------------------------
// C[M,N] = A @ B  (A half [M][K], B half [K][N]). Tile 128x128x32, 4 stages.
// All dims multiples of tile sizes. RND: round fp32 outputs to tf32.
template<bool RND>
__global__ __launch_bounds__(256, 2)
void hgemm_kernel(const __half* __restrict__ A,
                  const __half* __restrict__ B,
                  float* __restrict__ C,
                  int M, int N, int K,
                  int lda, int ldb, int ldc)
{
    constexpr int BK = 32, S = 4;

    const int bx = blockIdx.x, by = blockIdx.y;

    extern __shared__ __half hsm[];

    const int tid  = threadIdx.x;
    const int lane = tid & 31;
    const int warp = tid >> 5;
    const int gid  = lane >> 2;
    const int tig  = lane & 3;
    const int wr   = warp & 3;
    const int wc   = warp >> 2;
    const int rowBase = by * 128, colBase = bx * 128;
    const int wm = wr * 32, wn = wc * 64;

    const int tiles = K / BK;

    auto load_tile = [&](int st, int kt) {
        const int k0 = kt * BK;
        __half* As = hsm + st * STG_H;
        __half* Bs = As + ASTG_H;
        #pragma unroll
        for (int i = 0; i < 2; i++) {        // A: 128 rows x 64B (4 chunks/row)
            int c = tid + i * 256;
            int r = c >> 2, kc = (c & 3) * 8;
            cp16(smem_u32(As + r * APAD_H + kc),
                 A + (long)(rowBase + r) * lda + k0 + kc);
        }
        #pragma unroll
        for (int i = 0; i < 2; i++) {        // B: 32 rows x 256B (16 chunks/row)
            int c = tid + i * 256;
            int r = c >> 4, nc = (c & 15) * 8;
            cp16(smem_u32(Bs + r * BPAD_H + nc),
                 B + (long)(k0 + r) * ldb + colBase + nc);
        }
    };

    #pragma unroll
    for (int s = 0; s < S - 1; s++) {
        load_tile(s, s);
        asm volatile("cp.async.commit_group;\n");
    }

    float acc[2][8][4];
    #pragma unroll
    for (int i = 0; i < 2; i++)
        #pragma unroll
        for (int j = 0; j < 8; j++)
            #pragma unroll
            for (int v = 0; v < 4; v++) acc[i][j][v] = 0.0f;

    const int arow = lane & 15;          // ldsm A row within 16
    const int acol = (lane >> 4) * 8;    // ldsm A col (halves)

    for (int t = 0; t < tiles; t++) {
        asm volatile("cp.async.wait_group %0;\n" :: "n"(S - 2));
        __syncthreads();

        int tn = t + S - 1;
        if (tn < tiles) load_tile(tn % S, tn);
        asm volatile("cp.async.commit_group;\n");

        const __half* Asb = hsm + (t % S) * STG_H;
        const __half* Bsb = Asb + ASTG_H;

        #pragma unroll
        for (int ks = 0; ks < 2; ks++) {
            const int kb = ks * 16;
            unsigned af[2][4];
            unsigned a0 = smem_u32(Asb + (wm + arow) * APAD_H + kb + acol);
            ldsm_x4(af[0], a0);
            ldsm_x4(af[1], a0 + 16 * APAD_H * 2);

            unsigned b0 = smem_u32(Bsb + (kb + arow) * BPAD_H + wn + acol);
            #pragma unroll
            for (int p = 0; p < 4; p++) {
                unsigned bf[4];
                ldsm_x4t(bf, b0 + p * 32);   // +16 halves per pair
                mma_f16(acc[0][2 * p    ], af[0], bf + 0);
                mma_f16(acc[0][2 * p + 1], af[0], bf + 2);
                mma_f16(acc[1][2 * p    ], af[1], bf + 0);
                mma_f16(acc[1][2 * p + 1], af[1], bf + 2);
            }
        }
    }

    #pragma unroll
    for (int mt = 0; mt < 2; mt++) {
        #pragma unroll
        for (int nt = 0; nt < 8; nt++) {
            int gc = colBase + wn + nt * 8 + tig * 2;
            #pragma unroll
            for (int half = 0; half < 2; half++) {
                int gr = rowBase + wm + mt * 16 + gid + half * 8;
                float x0 = acc[mt][nt][half * 2];
                float x1 = acc[mt][nt][half * 2 + 1];
                if (RND) { x0 = f2tf32f(x0); x1 = f2tf32f(x1); }
                *reinterpret_cast<float2*>(&C[(long)gr * ldc + gc]) =
                    make_float2(x0, x1);
            }
        }
    }
}

// --------------------- fused flash attention kernel ------------------------
// q/kv/kr fp32 (tf32-rounded); ctx output written as half (feeds out-GEMM).
__global__ __launch_bounds__(256, 1)
void fused_attn_kernel(const float* __restrict__ q,
                       const float* __restrict__ kv,
                       const float* __restrict__ kr,
                       __half* __restrict__ ctx)
{
    extern __shared__ float sm[];
    float* Qs     = sm;
    float* KV     = sm + QS_F;
    float* Ps     = sm + QS_F + 3 * STG_F;
    float* row_m  = Ps + PS_F;
    float* row_l  = row_m + 128;
    float* row_r  = row_l + 128;
    float* rowred = row_r + 128;

    const int qt = 15 - blockIdx.x;
    const int h  = blockIdx.y;
    const long q0 = (long)qt * 128;

    const int tid  = threadIdx.x;
    const int lane = tid & 31;
    const int warp = tid >> 5;
    const int gid  = lane >> 2;
    const int tig  = lane & 3;
    const int wr   = warp & 3;
    const int wc   = warp >> 2;
    const int wm = wr * 32, wn = wc * 64;
    const int KVROW = H_ * (DN_ + DV_);

    if (tid < 128) { row_m[tid] = -1e30f; row_l[tid] = 0.0f; }

    const float* Qbase = q + q0 * (H_ * DQK_) + h * DQK_;
    #pragma unroll
    for (int i = 0; i < 24; i++) {
        int e = tid + i * 256;
        int r = e / 48;
        int fc = (e % 48) * 4;
        cp16(smem_u32(&Qs[r * QPAD + fc]), Qbase + (long)r * (H_ * DQK_) + fc);
    }
    asm volatile("cp.async.commit_group;\n");

    float Oacc[2][8][4];
    #pragma unroll
    for (int i = 0; i < 2; i++)
        #pragma unroll
        for (int j = 0; j < 8; j++)
            #pragma unroll
            for (int v = 0; v < 4; v++) Oacc[i][j][v] = 0.0f;

    for (int j = 0; j <= qt; j++) {
        const long key0 = (long)j * 128;
        const bool diag = (j == qt);

        auto load_k = [&](int st, int c) {
            const int d0 = c * 16;
            float* dst = &KV[st * STG_F];
            #pragma unroll
            for (int i = 0; i < 2; i++) {
                int e = tid + i * 256;
                int r = e >> 2;
                int fc = (e & 3) * 4;
                const float* src = (d0 < DN_)
                    ? kv + (key0 + r) * (long)KVROW + h * (DN_ + DV_) + d0 + fc
                    : kr + (key0 + r) * (long)DR_ + (d0 - DN_) + fc;
                cp16(smem_u32(dst + r * KPAD + fc), src);
            }
        };
        auto load_v = [&](int st, int c) {
            float* dst = &KV[st * STG_F];
            #pragma unroll
            for (int i = 0; i < 2; i++) {
                int e = tid + i * 256;
                int r = e >> 5;
                int fc = (e & 31) * 4;
                const float* src = kv + (key0 + c * 16 + r) * (long)KVROW
                                   + h * (DN_ + DV_) + DN_ + fc;
                cp16(smem_u32(dst + r * VPAD + fc), src);
            }
        };

        float Sacc[2][8][4];
        #pragma unroll
        for (int i = 0; i < 2; i++)
            #pragma unroll
            for (int jj = 0; jj < 8; jj++)
                #pragma unroll
                for (int v = 0; v < 4; v++) Sacc[i][jj][v] = 0.0f;

        load_k(0, 0);
        asm volatile("cp.async.commit_group;\n");
        for (int c = 0; c < 12; c++) {
            if (c + 1 < 12) {
                load_k((c + 1) % 3, c + 1);
                asm volatile("cp.async.commit_group;\n");
                asm volatile("cp.async.wait_group 1;\n");
            } else {
                asm volatile("cp.async.wait_group 0;\n");
            }
            __syncthreads();
            const float* Ks = &KV[(c % 3) * STG_F];
            const int dbase = c * 16;
            #pragma unroll
            for (int ks = 0; ks < 2; ks++) {
                const int kb = ks * 8;
                unsigned af[2][4];
                #pragma unroll
                for (int mt = 0; mt < 2; mt++) {
                    int m0 = wm + mt * 16;
                    af[mt][0] = ldu(&Qs[(m0 + gid    ) * QPAD + dbase + kb + tig    ]);
                    af[mt][1] = ldu(&Qs[(m0 + gid + 8) * QPAD + dbase + kb + tig    ]);
                    af[mt][2] = ldu(&Qs[(m0 + gid    ) * QPAD + dbase + kb + tig + 4]);
                    af[mt][3] = ldu(&Qs[(m0 + gid + 8) * QPAD + dbase + kb + tig + 4]);
                }
                #pragma unroll
                for (int nt = 0; nt < 8; nt++) {
                    int n0 = wn + nt * 8;
                    unsigned bf[2];
                    bf[0] = ldu(&Ks[(n0 + gid) * KPAD + kb + tig    ]);
                    bf[1] = ldu(&Ks[(n0 + gid) * KPAD + kb + tig + 4]);
                    mma_tf32(Sacc[0][nt], af[0], bf);
                    mma_tf32(Sacc[1][nt], af[1], bf);
                }
            }
        }

        load_v(0, 0);
        asm volatile("cp.async.commit_group;\n");

        #pragma unroll
        for (int mt = 0; mt < 2; mt++)
            #pragma unroll
            for (int nt = 0; nt < 8; nt++)
                #pragma unroll
                for (int v = 0; v < 4; v++) {
                    int rl = wm + mt * 16 + (v >> 1) * 8 + gid;
                    int cl = wn + nt * 8 + tig * 2 + (v & 1);
                    float s = Sacc[mt][nt][v] * SCALING_;
                    if (diag && cl > rl) s = -1e30f;
                    Sacc[mt][nt][v] = s;
                }

        #pragma unroll
        for (int mt = 0; mt < 2; mt++)
            #pragma unroll
            for (int half = 0; half < 2; half++) {
                int ri = wm + mt * 16 + half * 8 + gid;
                float mx = -1e30f;
                #pragma unroll
                for (int nt = 0; nt < 8; nt++) {
                    mx = fmaxf(mx, Sacc[mt][nt][half * 2]);
                    mx = fmaxf(mx, Sacc[mt][nt][half * 2 + 1]);
                }
                mx = fmaxf(mx, __shfl_xor_sync(0xffffffffu, mx, 1));
                mx = fmaxf(mx, __shfl_xor_sync(0xffffffffu, mx, 2));
                if (tig == 0) rowred[wc * 128 + ri] = mx;
            }
        __syncthreads();
        if (tid < 128) {
            float tm = fmaxf(rowred[tid], rowred[128 + tid]);
            float mo = row_m[tid];
            float mn = fmaxf(mo, tm);
            row_m[tid] = mn;
            row_r[tid] = __expf(mo - mn);
        }
        __syncthreads();

        #pragma unroll
        for (int mt = 0; mt < 2; mt++)
            #pragma unroll
            for (int half = 0; half < 2; half++) {
                int ri = wm + mt * 16 + half * 8 + gid;
                float m = row_m[ri];
                float rsc = row_r[ri];
                float s = 0.0f;
                #pragma unroll
                for (int nt = 0; nt < 8; nt++) {
                    float p0 = f2tf32f(__expf(Sacc[mt][nt][half * 2    ] - m));
                    float p1 = f2tf32f(__expf(Sacc[mt][nt][half * 2 + 1] - m));
                    s += p0 + p1;
                    int cl = wn + nt * 8 + tig * 2;
                    *reinterpret_cast<float2*>(&Ps[ri * PPAD + cl]) =
                        make_float2(p0, p1);
                    Oacc[mt][nt][half * 2    ] *= rsc;
                    Oacc[mt][nt][half * 2 + 1] *= rsc;
                }
                s += __shfl_xor_sync(0xffffffffu, s, 1);
                s += __shfl_xor_sync(0xffffffffu, s, 2);
                if (tig == 0) rowred[wc * 128 + ri] = s;
            }
        __syncthreads();
        if (tid < 128)
            row_l[tid] = row_l[tid] * row_r[tid] + rowred[tid] + rowred[128 + tid];
        __syncthreads();

        for (int c = 0; c < 8; c++) {
            if (c + 1 < 8) {
                load_v((13 + c) % 3, c + 1);
                asm volatile("cp.async.commit_group;\n");
                asm volatile("cp.async.wait_group 1;\n");
            } else {
                asm volatile("cp.async.wait_group 0;\n");
            }
            __syncthreads();
            const float* Vs = &KV[((12 + c) % 3) * STG_F];
            #pragma unroll
            for (int ks = 0; ks < 2; ks++) {
                const int kb = ks * 8;
                unsigned af[2][4];
                #pragma unroll
                for (int mt = 0; mt < 2; mt++) {
                    int m0 = wm + mt * 16;
                    int kc = c * 16 + kb + tig;
                    af[mt][0] = ldu(&Ps[(m0 + gid    ) * PPAD + kc    ]);
                    af[mt][1] = ldu(&Ps[(m0 + gid + 8) * PPAD + kc    ]);
                    af[mt][2] = ldu(&Ps[(m0 + gid    ) * PPAD + kc + 4]);
                    af[mt][3] = ldu(&Ps[(m0 + gid + 8) * PPAD + kc + 4]);
                }
                #pragma unroll
                for (int nt = 0; nt < 8; nt++) {
                    int n0 = wn + nt * 8;
                    unsigned bf[2];
                    bf[0] = ldu(&Vs[(kb + tig    ) * VPAD + n0 + gid]);
                    bf[1] = ldu(&Vs[(kb + tig + 4) * VPAD + n0 + gid]);
                    mma_tf32(Oacc[0][nt], af[0], bf);
                    mma_tf32(Oacc[1][nt], af[1], bf);
                }
            }
        }
        __syncthreads();
    }

    // epilogue: O /= l, write half ctx (feeds fp16 out-GEMM)
    #pragma unroll
    for (int mt = 0; mt < 2; mt++)
        #pragma unroll
        for (int half = 0; half < 2; half++) {
            int ri = wm + mt * 16 + half * 8 + gid;
            float inv = 1.0f / row_l[ri];
            long t = q0 + ri;
            #pragma unroll
            for (int nt = 0; nt < 8; nt++) {
                int cl = wn + nt * 8 + tig * 2;
                __half2 hv = __floats2half2_rn(Oacc[mt][nt][half * 2] * inv,
                                               Oacc[mt][nt][half * 2 + 1] * inv);
                *reinterpret_cast<__half2*>(&ctx[t * (H_ * DV_) + h * DV_ + cl]) = hv;
            }
        }
}

// ------------------------------ prep kernels --------------------------------
__global__ void tohalf_kernel(const float* __restrict__ in,
                              __half* __restrict__ out, long n)
{
    long i = ((long)blockIdx.x * blockDim.x + threadIdx.x) * 4;
    if (i < n) {
        float4 v = *reinterpret_cast<const float4*>(in + i);
        union { __half2 h[2]; uint2 u; } cv;
        cv.h[0] = __floats2half2_rn(v.x, v.y);
        cv.h[1] = __floats2half2_rn(v.z, v.w);
        *reinterpret_cast<uint2*>(out + i) = cv.u;
    }
}

// in [R][Cin] fp32 -> out [R][Cpad] half, zero-pad
__global__ void pad_tohalf_kernel(const float* __restrict__ in,
                                  __half* __restrict__ out, int R, int Cin, int Cpad)
{
    long i = (long)blockIdx.x * blockDim.x + threadIdx.x;
    long n = (long)R * Cpad;
    if (i < n) {
        int r = (int)(i / Cpad), c = (int)(i % Cpad);
        out[i] = (c < Cin) ? __float2half_rn(in[(long)r * Cin + c])
                           : __float2half_rn(0.0f);
    }
}

// ------------------------------ RMSNorm (half out) --------------------------
__global__ void rmsnorm_h_kernel(const float* __restrict__ x,
                                 const float* __restrict__ w,
                                 __half* __restrict__ y,
                                 int L, int ldx, int ldy)
{
    const int row = blockIdx.x, tid = threadIdx.x;
    const float* xr = x + (long)row * ldx;
    __half* yr = y + (long)row * ldy;

    __shared__ float red[256];
    float s = 0.0f;
    for (int i = tid; i < L; i += 256) { float v = xr[i]; s += v * v; }
    red[tid] = s; __syncthreads();
    for (int o = 128; o > 0; o >>= 1) {
        if (tid < o) red[tid] += red[tid + o];
        __syncthreads();
    }
    const float scale = rsqrtf(red[0] / (float)L + EPS_);
    for (int i = tid; i < L; i += 256)
        yr[i] = __float2half_rn(xr[i] * scale * w[i]);
}

// -------------------------------- RoPE -------------------------------------
// output tf32-rounded (feeds attention tf32 mma)
__global__ void rope_kernel(const float* __restrict__ x, float* __restrict__ o,
                            const float* __restrict__ cosT,
                            const float* __restrict__ sinT,
                            long sxt, int sxh, long sot, int soh)
{
    const int h = blockIdx.x, t = blockIdx.y, i = threadIdx.x;  // i < 64
    const float* xp = x + (long)t * sxt + (long)h * sxh;
    float* op = o + (long)t * sot + (long)h * soh;

    __shared__ float xs[64];
    __shared__ float ys[64];
    xs[i] = xp[i];
    __syncthreads();
    float y = (i < 32) ? xs[2 * i] : xs[2 * (i - 32) + 1];
    ys[i] = y;
    __syncthreads();
    float rot = (i < 32) ? -ys[i + 32] : ys[i - 32];
    op[i] = f2tf32f(y * cosT[(long)t * DR_ + i] + rot * sinT[(long)t * DR_ + i]);
}

// ------------------------------- launch ------------------------------------
extern "C" void kernel_launch(void* const* d_in, const int* in_sizes, int n_in,
                              void* d_out, int out_size)
{
    const float* hidden = (const float*)d_in[0];
    const float* cosT   = (const float*)d_in[1];
    const float* sinT   = (const float*)d_in[2];
    const float* wq_a   = (const float*)d_in[3];
    const float* q_ln   = (const float*)d_in[4];
    const float* wq_b   = (const float*)d_in[5];
    const float* wkv_a  = (const float*)d_in[6];
    const float* kv_ln  = (const float*)d_in[7];
    const float* wkv_b  = (const float*)d_in[8];
    const float* wo     = (const float*)d_in[9];
    float* out = (float*)d_out;

    static __half *hidH = nullptr, *qa16 = nullptr, *cn16 = nullptr,
                  *ctx16 = nullptr, *wqa = nullptr, *wqb = nullptr,
                  *wkva = nullptr, *wkvb = nullptr, *woH = nullptr;
    static float *qa32 = nullptr, *q = nullptr, *ckv = nullptr,
                 *kv = nullptr, *kr = nullptr;
    if (!qa32) {
        cudaGetSymbolAddress((void**)&hidH,  g_hidH);
        cudaGetSymbolAddress((void**)&qa32,  g_qa32);
        cudaGetSymbolAddress((void**)&qa16,  g_qa16);
        cudaGetSymbolAddress((void**)&q,     g_q);
        cudaGetSymbolAddress((void**)&ckv,   g_ckv);
        cudaGetSymbolAddress((void**)&cn16,  g_cn16);
        cudaGetSymbolAddress((void**)&kv,    g_kv);
        cudaGetSymbolAddress((void**)&kr,    g_kr);
        cudaGetSymbolAddress((void**)&ctx16, g_ctx16);
        cudaGetSymbolAddress((void**)&wqa,   g_wqa);
        cudaGetSymbolAddress((void**)&wqb,   g_wqb);
        cudaGetSymbolAddress((void**)&wkva,  g_wkva);
        cudaGetSymbolAddress((void**)&wkvb,  g_wkvb);
        cudaGetSymbolAddress((void**)&woH,   g_wo);
        cudaFuncSetAttribute(hgemm_kernel<false>,
                             cudaFuncAttributeMaxDynamicSharedMemorySize, GSMEM_BYTES);
        cudaFuncSetAttribute(hgemm_kernel<true>,
                             cudaFuncAttributeMaxDynamicSharedMemorySize, GSMEM_BYTES);
        cudaFuncSetAttribute(fused_attn_kernel,
                             cudaFuncAttributeMaxDynamicSharedMemorySize, FUSED_SMEM);
    }

    const dim3 blk(256);

    // 0) prep: convert hidden + weights to fp16 (wkv_a padded to 640)
    tohalf_kernel<<<(int)(((long)T_ * HIDDEN_ / 4 + 255) / 256), 256>>>(
        hidden, hidH, (long)T_ * HIDDEN_);
    tohalf_kernel<<<(int)(((long)HIDDEN_ * QL_ / 4 + 255) / 256), 256>>>(
        wq_a, wqa, (long)HIDDEN_ * QL_);
    tohalf_kernel<<<(int)(((long)QL_ * H_ * DQK_ / 4 + 255) / 256), 256>>>(
        wq_b, wqb, (long)QL_ * H_ * DQK_);
    pad_tohalf_kernel<<<(int)(((long)HIDDEN_ * CKVP_ + 255) / 256), 256>>>(
        wkv_a, wkva, HIDDEN_, KVL_ + DR_, CKVP_);
    tohalf_kernel<<<(int)(((long)KVL_ * H_ * (DN_ + DV_) / 4 + 255) / 256), 256>>>(
        wkv_b, wkvb, (long)KVL_ * H_ * (DN_ + DV_));
    tohalf_kernel<<<(int)(((long)(H_ * DV_) * HIDDEN_ / 4 + 255) / 256), 256>>>(
        wo, woH, (long)(H_ * DV_) * HIDDEN_);

    // 1) q_a = hid @ wq_a           [2048 x 1536], K=5120
    hgemm_kernel<false><<<dim3(QL_ / 128, 16), blk, GSMEM_BYTES>>>(
        hidH, wqa, qa32, T_, QL_, HIDDEN_, HIDDEN_, QL_, QL_);
    // 2) rmsnorm(q_a) -> half
    rmsnorm_h_kernel<<<T_, 256>>>(qa32, q_ln, qa16, QL_, QL_, QL_);
    // 3) q = q_a_n @ wq_b           [2048 x 6144], K=1536 (tf32-rounded out)
    hgemm_kernel<true><<<dim3(H_ * DQK_ / 128, 16), blk, GSMEM_BYTES>>>(
        qa16, wqb, q, T_, H_ * DQK_, QL_, QL_, H_ * DQK_, H_ * DQK_);
    // 4) ckv = hid @ wkv_a          [2048 x 640], K=5120
    hgemm_kernel<false><<<dim3(CKVP_ / 128, 16), blk, GSMEM_BYTES>>>(
        hidH, wkva, ckv, T_, CKVP_, HIDDEN_, HIDDEN_, CKVP_, CKVP_);
    // 5) cn = rmsnorm(ckv[:, :512]) -> half
    rmsnorm_h_kernel<<<T_, 256>>>(ckv, kv_ln, cn16, KVL_, CKVP_, KVL_);
    // 6) kv = cn @ wkv_b            [2048 x 8192], K=512 (tf32-rounded out)
    hgemm_kernel<true><<<dim3(H_ * (DN_ + DV_) / 128, 16), blk, GSMEM_BYTES>>>(
        cn16, wkvb, kv, T_, H_ * (DN_ + DV_), KVL_,
        KVL_, H_ * (DN_ + DV_), H_ * (DN_ + DV_));
    // 7) RoPE on q_pe (in place, tf32-rounded)
    rope_kernel<<<dim3(H_, T_), 64>>>(q + DN_, q + DN_, cosT, sinT,
                                      H_ * DQK_, DQK_, H_ * DQK_, DQK_);
    // 8) RoPE on k_pe -> kr (tf32-rounded)
    rope_kernel<<<dim3(1, T_), 64>>>(ckv + KVL_, kr, cosT, sinT,
                                     CKVP_, 0, DR_, 0);
    // 9) fused attention: ctx(half) = softmax(QK^T) @ V
    fused_attn_kernel<<<dim3(16, H_), blk, FUSED_SMEM>>>(q, kv, kr, ctx16);
    // 10) out = ctx @ wo            [2048 x 5120], K=1024
    hgemm_kernel<false><<<dim3(HIDDEN_ / 128, 16), blk, GSMEM_BYTES>>>(
        ctx16, woH, out, T_, HIDDEN_, H_ * DV_, H_ * DV_, HIDDEN_, HIDDEN_);
}

// round 8
// speedup vs baseline: 15.1504x; 1.2487x over previous
#include <cuda_runtime.h>
#include <cuda_fp16.h>
#include <math.h>

// ---------------------------------------------------------------------------
// DeepSeek V2 MLA attention prefill — fp16 mma.sync m16n8k16 + ldmatrix
// everywhere (dense GEMMs and fused flash attention), fp32 accumulate.
// ---------------------------------------------------------------------------

namespace {
constexpr int T_      = 2048;
constexpr int H_      = 32;
constexpr int HIDDEN_ = 5120;
constexpr int QL_     = 1536;
constexpr int KVL_    = 512;
constexpr int DN_     = 128;
constexpr int DR_     = 64;
constexpr int DQK_    = 192;
constexpr int DV_     = 128;
constexpr int CKVP_   = 640;   // ckv scratch width (multiple of 128)
constexpr float EPS_  = 1e-6f;
constexpr float SCALING_ = 0.07216878364870323f;  // 192^-0.5

// fp16 dense GEMM smem (halves)
constexpr int APAD_H = 40;
constexpr int BPAD_H = 136;
constexpr int ASTG_H = 128 * APAD_H;        // 5120
constexpr int BSTG_H = 32 * BPAD_H;         // 4352
constexpr int STG_H  = ASTG_H + BSTG_H;     // 9472 halves
constexpr int GSMEM_BYTES = 4 * STG_H * 2;  // 75776 B

// fused attention smem (halves + trailing float reductions)
constexpr int QPAD_A  = 200;                   // Q row stride (halves)
constexpr int KPAD_A  = 40;                    // K chunk row stride
constexpr int VPAD_A  = 136;                   // V chunk row stride
constexpr int PPAD_A  = 136;                   // P row stride
constexpr int AQ_H    = 128 * QPAD_A;          // 25600
constexpr int ASTG_A  = 5120;                  // ring stage (max: 128*40, 32*136)
constexpr int APS_H   = 128 * PPAD_A;          // 17408
constexpr int AHALF_T = AQ_H + 3 * ASTG_A + APS_H;  // 58368 halves
constexpr int FUSED_SMEM = AHALF_T * 2 + 640 * 4;   // 119296 B
}

// ------------------------- scratch (static device) -------------------------
__device__ __half g_hidH[(long)T_ * HIDDEN_];
__device__ float  g_qa32[(long)T_ * QL_];
__device__ __half g_qa16[(long)T_ * QL_];
__device__ __half g_q16[(long)T_ * H_ * DQK_];
__device__ float  g_ckv[(long)T_ * CKVP_];
__device__ __half g_cn16[(long)T_ * KVL_];
__device__ __half g_kv16[(long)T_ * H_ * (DN_ + DV_)];
__device__ __half g_kr16[(long)T_ * DR_];
__device__ __half g_ctx16[(long)T_ * H_ * DV_];
// fp16 weights (same layout as inputs; wkv_a padded to 640 cols)
__device__ __half g_wqa [(long)HIDDEN_ * QL_];
__device__ __half g_wqb [(long)QL_ * (H_ * DQK_)];
__device__ __half g_wkva[(long)HIDDEN_ * CKVP_];
__device__ __half g_wkvb[(long)KVL_ * (H_ * (DN_ + DV_))];
__device__ __half g_wo  [(long)(H_ * DV_) * HIDDEN_];

// ------------------------------ helpers ------------------------------------
__device__ __forceinline__ void mma_f16(float* d, const unsigned* a, const unsigned* b) {
    asm volatile(
        "mma.sync.aligned.m16n8k16.row.col.f32.f16.f16.f32 "
        "{%0,%1,%2,%3}, {%4,%5,%6,%7}, {%8,%9}, {%0,%1,%2,%3};"
        : "+f"(d[0]), "+f"(d[1]), "+f"(d[2]), "+f"(d[3])
        : "r"(a[0]), "r"(a[1]), "r"(a[2]), "r"(a[3]),
          "r"(b[0]), "r"(b[1]));
}

__device__ __forceinline__ void ldsm_x4(unsigned* r, unsigned addr) {
    asm volatile("ldmatrix.sync.aligned.m8n8.x4.shared.b16 {%0,%1,%2,%3}, [%4];"
                 : "=r"(r[0]), "=r"(r[1]), "=r"(r[2]), "=r"(r[3]) : "r"(addr));
}
__device__ __forceinline__ void ldsm_x4t(unsigned* r, unsigned addr) {
    asm volatile("ldmatrix.sync.aligned.m8n8.x4.trans.shared.b16 {%0,%1,%2,%3}, [%4];"
                 : "=r"(r[0]), "=r"(r[1]), "=r"(r[2]), "=r"(r[3]) : "r"(addr));
}

__device__ __forceinline__ unsigned smem_u32(const void* p) {
    return (unsigned)__cvta_generic_to_shared(p);
}
__device__ __forceinline__ void cp16(unsigned dst, const void* src) {
    asm volatile("cp.async.cg.shared.global [%0], [%1], 16;\n" :: "r"(dst), "l"(src));
}

// ------------------------------- FP16 GEMM ---------------------------------
// C[M,N] = A @ B  (A half [M][K], B half [K][N]). Tile 128x128x32, 4 stages.
// OUT: 0 = float C, 1 = half C.
template<int OUT>
__global__ __launch_bounds__(256, 2)
void hgemm_kernel(const __half* __restrict__ A,
                  const __half* __restrict__ B,
                  void* __restrict__ Cv,
                  int M, int N, int K,
                  int lda, int ldb, int ldc)
{
    constexpr int BK = 32, S = 4;

    const int bx = blockIdx.x, by = blockIdx.y;

    extern __shared__ __half hsm[];

    const int tid  = threadIdx.x;
    const int lane = tid & 31;
    const int warp = tid >> 5;
    const int gid  = lane >> 2;
    const int tig  = lane & 3;
    const int wr   = warp & 3;
    const int wc   = warp >> 2;
    const int rowBase = by * 128, colBase = bx * 128;
    const int wm = wr * 32, wn = wc * 64;

    const int tiles = K / BK;

    auto load_tile = [&](int st, int kt) {
        const int k0 = kt * BK;
        __half* As = hsm + st * STG_H;
        __half* Bs = As + ASTG_H;
        #pragma unroll
        for (int i = 0; i < 2; i++) {
            int c = tid + i * 256;
            int r = c >> 2, kc = (c & 3) * 8;
            cp16(smem_u32(As + r * APAD_H + kc),
                 A + (long)(rowBase + r) * lda + k0 + kc);
        }
        #pragma unroll
        for (int i = 0; i < 2; i++) {
            int c = tid + i * 256;
            int r = c >> 4, nc = (c & 15) * 8;
            cp16(smem_u32(Bs + r * BPAD_H + nc),
                 B + (long)(k0 + r) * ldb + colBase + nc);
        }
    };

    #pragma unroll
    for (int s = 0; s < S - 1; s++) {
        load_tile(s, s);
        asm volatile("cp.async.commit_group;\n");
    }

    float acc[2][8][4];
    #pragma unroll
    for (int i = 0; i < 2; i++)
        #pragma unroll
        for (int j = 0; j < 8; j++)
            #pragma unroll
            for (int v = 0; v < 4; v++) acc[i][j][v] = 0.0f;

    const int arow = lane & 15;
    const int acol = (lane >> 4) * 8;

    for (int t = 0; t < tiles; t++) {
        asm volatile("cp.async.wait_group %0;\n" :: "n"(S - 2));
        __syncthreads();

        int tn = t + S - 1;
        if (tn < tiles) load_tile(tn % S, tn);
        asm volatile("cp.async.commit_group;\n");

        const __half* Asb = hsm + (t % S) * STG_H;
        const __half* Bsb = Asb + ASTG_H;

        #pragma unroll
        for (int ks = 0; ks < 2; ks++) {
            const int kb = ks * 16;
            unsigned af[2][4];
            unsigned a0 = smem_u32(Asb + (wm + arow) * APAD_H + kb + acol);
            ldsm_x4(af[0], a0);
            ldsm_x4(af[1], a0 + 16 * APAD_H * 2);

            unsigned b0 = smem_u32(Bsb + (kb + arow) * BPAD_H + wn + acol);
            #pragma unroll
            for (int p = 0; p < 4; p++) {
                unsigned bf[4];
                ldsm_x4t(bf, b0 + p * 32);
                mma_f16(acc[0][2 * p    ], af[0], bf + 0);
                mma_f16(acc[0][2 * p + 1], af[0], bf + 2);
                mma_f16(acc[1][2 * p    ], af[1], bf + 0);
                mma_f16(acc[1][2 * p + 1], af[1], bf + 2);
            }
        }
    }

    #pragma unroll
    for (int mt = 0; mt < 2; mt++) {
        #pragma unroll
        for (int nt = 0; nt < 8; nt++) {
            int gc = colBase + wn + nt * 8 + tig * 2;
            #pragma unroll
            for (int half = 0; half < 2; half++) {
                int gr = rowBase + wm + mt * 16 + gid + half * 8;
                float x0 = acc[mt][nt][half * 2];
                float x1 = acc[mt][nt][half * 2 + 1];
                if (OUT == 0) {
                    float* C = (float*)Cv;
                    *reinterpret_cast<float2*>(&C[(long)gr * ldc + gc]) =
                        make_float2(x0, x1);
                } else {
                    __half* C = (__half*)Cv;
                    *reinterpret_cast<__half2*>(&C[(long)gr * ldc + gc]) =
                        __floats2half2_rn(x0, x1);
                }
            }
        }
    }
}

// --------------------- fused flash attention (fp16 mma) --------------------
// q/kv/kr half; ctx half. One CTA per (q-tile 128 rows, head).
__global__ __launch_bounds__(256, 1)
void fused_attn_kernel(const __half* __restrict__ q,
                       const __half* __restrict__ kv,
                       const __half* __restrict__ kr,
                       __half* __restrict__ ctx)
{
    extern __shared__ __half hs[];
    __half* Qs   = hs;                       // 128 x QPAD_A
    __half* RING = hs + AQ_H;                // 3 x ASTG_A
    __half* Ps   = hs + AQ_H + 3 * ASTG_A;   // 128 x PPAD_A
    float* fbase  = reinterpret_cast<float*>(hs + AHALF_T);
    float* row_m  = fbase;
    float* row_l  = fbase + 128;
    float* row_r  = fbase + 256;
    float* rowred = fbase + 384;             // 256 floats

    const int qt = 15 - blockIdx.x;
    const int h  = blockIdx.y;
    const long q0 = (long)qt * 128;

    const int tid  = threadIdx.x;
    const int lane = tid & 31;
    const int warp = tid >> 5;
    const int gid  = lane >> 2;
    const int tig  = lane & 3;
    const int wr   = warp & 3;
    const int wc   = warp >> 2;
    const int wm = wr * 32, wn = wc * 64;
    const int KVROW = H_ * (DN_ + DV_);      // 8192

    const int arow = lane & 15;
    const int acol = (lane >> 4) * 8;
    const int krow_off = ((lane >> 4) << 3) + (lane & 7);
    const int kcol_off = ((lane >> 3) & 1) << 3;

    if (tid < 128) { row_m[tid] = -1e30f; row_l[tid] = 0.0f; }

    // ---- load Q tile [128 x 192] halves (24 16B chunks per row)
    const __half* Qbase = q + q0 * (H_ * DQK_) + h * DQK_;
    #pragma unroll
    for (int i = 0; i < 12; i++) {
        int e = tid + i * 256;
        int r = e / 24;
        int fc = (e % 24) * 8;
        cp16(smem_u32(Qs + r * QPAD_A + fc), Qbase + (long)r * (H_ * DQK_) + fc);
    }
    asm volatile("cp.async.commit_group;\n");

    float Oacc[2][8][4];
    #pragma unroll
    for (int i = 0; i < 2; i++)
        #pragma unroll
        for (int j = 0; j < 8; j++)
            #pragma unroll
            for (int v = 0; v < 4; v++) Oacc[i][j][v] = 0.0f;

    for (int j = 0; j <= qt; j++) {
        const long key0 = (long)j * 128;
        const bool diag = (j == qt);

        // K chunk c: 128 keys x 32 d  (d0 = 32c; chunks 0-3 nope, 4-5 rope)
        auto load_k = [&](int st, int c) {
            const int d0 = c * 32;
            __half* dst = RING + st * ASTG_A;
            #pragma unroll
            for (int i = 0; i < 2; i++) {
                int e = tid + i * 256;
                int r = e >> 2;
                int fc = (e & 3) * 8;
                const __half* src = (d0 < DN_)
                    ? kv + (key0 + r) * (long)KVROW + h * (DN_ + DV_) + d0 + fc
                    : kr + (key0 + r) * (long)DR_ + (d0 - DN_) + fc;
                cp16(smem_u32(dst + r * KPAD_A + fc), src);
            }
        };
        // V chunk c: 32 keys x 128 dv
        auto load_v = [&](int st, int c) {
            __half* dst = RING + st * ASTG_A;
            #pragma unroll
            for (int i = 0; i < 2; i++) {
                int e = tid + i * 256;
                int r = e >> 4;
                int fc = (e & 15) * 8;
                const __half* src = kv + (key0 + c * 32 + r) * (long)KVROW
                                    + h * (DN_ + DV_) + DN_ + fc;
                cp16(smem_u32(dst + r * VPAD_A + fc), src);
            }
        };

        float Sacc[2][8][4];
        #pragma unroll
        for (int i = 0; i < 2; i++)
            #pragma unroll
            for (int jj = 0; jj < 8; jj++)
                #pragma unroll
                for (int v = 0; v < 4; v++) Sacc[i][jj][v] = 0.0f;

        // ---- S = Q @ K^T : 6 d-chunks of 32
        load_k(0, 0);
        asm volatile("cp.async.commit_group;\n");
        for (int c = 0; c < 6; c++) {
            if (c + 1 < 6) {
                load_k((c + 1) % 3, c + 1);
                asm volatile("cp.async.commit_group;\n");
                asm volatile("cp.async.wait_group 1;\n");
            } else {
                asm volatile("cp.async.wait_group 0;\n");
            }
            __syncthreads();
            const __half* Ks = RING + (c % 3) * ASTG_A;
            const int dbase = c * 32;
            #pragma unroll
            for (int ks = 0; ks < 2; ks++) {
                const int kb = ks * 16;
                unsigned af[2][4];
                unsigned a0 = smem_u32(Qs + (wm + arow) * QPAD_A + dbase + kb + acol);
                ldsm_x4(af[0], a0);
                ldsm_x4(af[1], a0 + 16 * QPAD_A * 2);
                #pragma unroll
                for (int nt2 = 0; nt2 < 4; nt2++) {
                    unsigned bf[4];
                    unsigned b0 = smem_u32(Ks + (wn + nt2 * 16 + krow_off) * KPAD_A
                                           + kb + kcol_off);
                    ldsm_x4(bf, b0);    // non-trans: K rows are d-major
                    mma_f16(Sacc[0][2 * nt2    ], af[0], bf + 0);
                    mma_f16(Sacc[0][2 * nt2 + 1], af[0], bf + 2);
                    mma_f16(Sacc[1][2 * nt2    ], af[1], bf + 0);
                    mma_f16(Sacc[1][2 * nt2 + 1], af[1], bf + 2);
                }
            }
        }

        // prefetch V chunk 0 (stage 0) — overlaps softmax
        load_v(0, 0);
        asm volatile("cp.async.commit_group;\n");

        // ---- scale + causal mask
        #pragma unroll
        for (int mt = 0; mt < 2; mt++)
            #pragma unroll
            for (int nt = 0; nt < 8; nt++)
                #pragma unroll
                for (int v = 0; v < 4; v++) {
                    int rl = wm + mt * 16 + (v >> 1) * 8 + gid;
                    int cl = wn + nt * 8 + tig * 2 + (v & 1);
                    float s = Sacc[mt][nt][v] * SCALING_;
                    if (diag && cl > rl) s = -1e30f;
                    Sacc[mt][nt][v] = s;
                }

        // ---- row max
        #pragma unroll
        for (int mt = 0; mt < 2; mt++)
            #pragma unroll
            for (int half = 0; half < 2; half++) {
                int ri = wm + mt * 16 + half * 8 + gid;
                float mx = -1e30f;
                #pragma unroll
                for (int nt = 0; nt < 8; nt++) {
                    mx = fmaxf(mx, Sacc[mt][nt][half * 2]);
                    mx = fmaxf(mx, Sacc[mt][nt][half * 2 + 1]);
                }
                mx = fmaxf(mx, __shfl_xor_sync(0xffffffffu, mx, 1));
                mx = fmaxf(mx, __shfl_xor_sync(0xffffffffu, mx, 2));
                if (tig == 0) rowred[wc * 128 + ri] = mx;
            }
        __syncthreads();
        if (tid < 128) {
            float tm = fmaxf(rowred[tid], rowred[128 + tid]);
            float mo = row_m[tid];
            float mn = fmaxf(mo, tm);
            row_m[tid] = mn;
            row_r[tid] = __expf(mo - mn);
        }
        __syncthreads();

        // ---- exp, P (half) write, row sum (of rounded), O rescale
        #pragma unroll
        for (int mt = 0; mt < 2; mt++)
            #pragma unroll
            for (int half = 0; half < 2; half++) {
                int ri = wm + mt * 16 + half * 8 + gid;
                float m = row_m[ri];
                float rsc = row_r[ri];
                float s = 0.0f;
                #pragma unroll
                for (int nt = 0; nt < 8; nt++) {
                    float p0 = __expf(Sacc[mt][nt][half * 2    ] - m);
                    float p1 = __expf(Sacc[mt][nt][half * 2 + 1] - m);
                    __half2 hv = __floats2half2_rn(p0, p1);
                    int cl = wn + nt * 8 + tig * 2;
                    *reinterpret_cast<__half2*>(&Ps[ri * PPAD_A + cl]) = hv;
                    float2 pr = __half22float2(hv);
                    s += pr.x + pr.y;
                    Oacc[mt][nt][half * 2    ] *= rsc;
                    Oacc[mt][nt][half * 2 + 1] *= rsc;
                }
                s += __shfl_xor_sync(0xffffffffu, s, 1);
                s += __shfl_xor_sync(0xffffffffu, s, 2);
                if (tig == 0) rowred[wc * 128 + ri] = s;
            }
        __syncthreads();
        if (tid < 128)
            row_l[tid] = row_l[tid] * row_r[tid] + rowred[tid] + rowred[128 + tid];
        __syncthreads();

        // ---- O += P @ V : 4 key-chunks of 32
        for (int c = 0; c < 4; c++) {
            if (c + 1 < 4) {
                load_v((c + 1) % 3, c + 1);
                asm volatile("cp.async.commit_group;\n");
                asm volatile("cp.async.wait_group 1;\n");
            } else {
                asm volatile("cp.async.wait_group 0;\n");
            }
            __syncthreads();
            const __half* Vs = RING + (c % 3) * ASTG_A;
            #pragma unroll
            for (int ks = 0; ks < 2; ks++) {
                const int kb = ks * 16;
                const int kc = c * 32 + kb;
                unsigned af[2][4];
                unsigned a0 = smem_u32(Ps + (wm + arow) * PPAD_A + kc + acol);
                ldsm_x4(af[0], a0);
                ldsm_x4(af[1], a0 + 16 * PPAD_A * 2);
                unsigned vb = smem_u32(Vs + (kb + arow) * VPAD_A + wn + acol);
                #pragma unroll
                for (int p = 0; p < 4; p++) {
                    unsigned bf[4];
                    ldsm_x4t(bf, vb + p * 32);
                    mma_f16(Oacc[0][2 * p    ], af[0], bf + 0);
                    mma_f16(Oacc[0][2 * p + 1], af[0], bf + 2);
                    mma_f16(Oacc[1][2 * p    ], af[1], bf + 0);
                    mma_f16(Oacc[1][2 * p + 1], af[1], bf + 2);
                }
            }
        }
        __syncthreads();   // protect ring + Ps before next j
    }

    // ---- epilogue: O /= l, write half ctx
    #pragma unroll
    for (int mt = 0; mt < 2; mt++)
        #pragma unroll
        for (int half = 0; half < 2; half++) {
            int ri = wm + mt * 16 + half * 8 + gid;
            float inv = 1.0f / row_l[ri];
            long t = q0 + ri;
            #pragma unroll
            for (int nt = 0; nt < 8; nt++) {
                int cl = wn + nt * 8 + tig * 2;
                __half2 hv = __floats2half2_rn(Oacc[mt][nt][half * 2] * inv,
                                               Oacc[mt][nt][half * 2 + 1] * inv);
                *reinterpret_cast<__half2*>(&ctx[t * (H_ * DV_) + h * DV_ + cl]) = hv;
            }
        }
}

// ------------------------------ prep kernels --------------------------------
__global__ void tohalf_kernel(const float* __restrict__ in,
                              __half* __restrict__ out, long n)
{
    long i = ((long)blockIdx.x * blockDim.x + threadIdx.x) * 4;
    if (i < n) {
        float4 v = *reinterpret_cast<const float4*>(in + i);
        union { __half2 h[2]; uint2 u; } cv;
        cv.h[0] = __floats2half2_rn(v.x, v.y);
        cv.h[1] = __floats2half2_rn(v.z, v.w);
        *reinterpret_cast<uint2*>(out + i) = cv.u;
    }
}

__global__ void pad_tohalf_kernel(const float* __restrict__ in,
                                  __half* __restrict__ out, int R, int Cin, int Cpad)
{
    long i = (long)blockIdx.x * blockDim.x + threadIdx.x;
    long n = (long)R * Cpad;
    if (i < n) {
        int r = (int)(i / Cpad), c = (int)(i % Cpad);
        out[i] = (c < Cin) ? __float2half_rn(in[(long)r * Cin + c])
                           : __float2half_rn(0.0f);
    }
}

// ------------------------------ RMSNorm (half out) --------------------------
__global__ void rmsnorm_h_kernel(const float* __restrict__ x,
                                 const float* __restrict__ w,
                                 __half* __restrict__ y,
                                 int L, int ldx, int ldy)
{
    const int row = blockIdx.x, tid = threadIdx.x;
    const float* xr = x + (long)row * ldx;
    __half* yr = y + (long)row * ldy;

    __shared__ float red[256];
    float s = 0.0f;
    for (int i = tid; i < L; i += 256) { float v = xr[i]; s += v * v; }
    red[tid] = s; __syncthreads();
    for (int o = 128; o > 0; o >>= 1) {
        if (tid < o) red[tid] += red[tid + o];
        __syncthreads();
    }
    const float scale = rsqrtf(red[0] / (float)L + EPS_);
    for (int i = tid; i < L; i += 256)
        yr[i] = __float2half_rn(xr[i] * scale * w[i]);
}

// -------------------------------- RoPE (half out) ---------------------------
template<typename Tin>
__global__ void rope_kernel(const Tin* __restrict__ x, __half* __restrict__ o,
                            const float* __restrict__ cosT,
                            const float* __restrict__ sinT,
                            long sxt, int sxh, long sot, int soh)
{
    const int h = blockIdx.x, t = blockIdx.y, i = threadIdx.x;  // i < 64
    const Tin* xp = x + (long)t * sxt + (long)h * sxh;
    __half* op = o + (long)t * sot + (long)h * soh;

    __shared__ float xs[64];
    __shared__ float ys[64];
    xs[i] = (float)xp[i];
    __syncthreads();
    float y = (i < 32) ? xs[2 * i] : xs[2 * (i - 32) + 1];
    ys[i] = y;
    __syncthreads();
    float rot = (i < 32) ? -ys[i + 32] : ys[i - 32];
    op[i] = __float2half_rn(y * cosT[(long)t * DR_ + i]
                            + rot * sinT[(long)t * DR_ + i]);
}

// ------------------------------- launch ------------------------------------
extern "C" void kernel_launch(void* const* d_in, const int* in_sizes, int n_in,
                              void* d_out, int out_size)
{
    const float* hidden = (const float*)d_in[0];
    const float* cosT   = (const float*)d_in[1];
    const float* sinT   = (const float*)d_in[2];
    const float* wq_a   = (const float*)d_in[3];
    const float* q_ln   = (const float*)d_in[4];
    const float* wq_b   = (const float*)d_in[5];
    const float* wkv_a  = (const float*)d_in[6];
    const float* kv_ln  = (const float*)d_in[7];
    const float* wkv_b  = (const float*)d_in[8];
    const float* wo     = (const float*)d_in[9];
    float* out = (float*)d_out;

    static __half *hidH = nullptr, *qa16 = nullptr, *q16 = nullptr,
                  *cn16 = nullptr, *kv16 = nullptr, *kr16 = nullptr,
                  *ctx16 = nullptr, *wqa = nullptr, *wqb = nullptr,
                  *wkva = nullptr, *wkvb = nullptr, *woH = nullptr;
    static float *qa32 = nullptr, *ckv = nullptr;
    if (!qa32) {
        cudaGetSymbolAddress((void**)&hidH,  g_hidH);
        cudaGetSymbolAddress((void**)&qa32,  g_qa32);
        cudaGetSymbolAddress((void**)&qa16,  g_qa16);
        cudaGetSymbolAddress((void**)&q16,   g_q16);
        cudaGetSymbolAddress((void**)&ckv,   g_ckv);
        cudaGetSymbolAddress((void**)&cn16,  g_cn16);
        cudaGetSymbolAddress((void**)&kv16,  g_kv16);
        cudaGetSymbolAddress((void**)&kr16,  g_kr16);
        cudaGetSymbolAddress((void**)&ctx16, g_ctx16);
        cudaGetSymbolAddress((void**)&wqa,   g_wqa);
        cudaGetSymbolAddress((void**)&wqb,   g_wqb);
        cudaGetSymbolAddress((void**)&wkva,  g_wkva);
        cudaGetSymbolAddress((void**)&wkvb,  g_wkvb);
        cudaGetSymbolAddress((void**)&woH,   g_wo);
        cudaFuncSetAttribute(hgemm_kernel<0>,
                             cudaFuncAttributeMaxDynamicSharedMemorySize, GSMEM_BYTES);
        cudaFuncSetAttribute(hgemm_kernel<1>,
                             cudaFuncAttributeMaxDynamicSharedMemorySize, GSMEM_BYTES);
        cudaFuncSetAttribute(fused_attn_kernel,
                             cudaFuncAttributeMaxDynamicSharedMemorySize, FUSED_SMEM);
    }

    const dim3 blk(256);

    // 0) prep: fp16 copies of hidden + weights (wkv_a padded to 640)
    tohalf_kernel<<<(int)(((long)T_ * HIDDEN_ / 4 + 255) / 256), 256>>>(
        hidden, hidH, (long)T_ * HIDDEN_);
    tohalf_kernel<<<(int)(((long)HIDDEN_ * QL_ / 4 + 255) / 256), 256>>>(
        wq_a, wqa, (long)HIDDEN_ * QL_);
    tohalf_kernel<<<(int)(((long)QL_ * H_ * DQK_ / 4 + 255) / 256), 256>>>(
        wq_b, wqb, (long)QL_ * H_ * DQK_);
    pad_tohalf_kernel<<<(int)(((long)HIDDEN_ * CKVP_ + 255) / 256), 256>>>(
        wkv_a, wkva, HIDDEN_, KVL_ + DR_, CKVP_);
    tohalf_kernel<<<(int)(((long)KVL_ * H_ * (DN_ + DV_) / 4 + 255) / 256), 256>>>(
        wkv_b, wkvb, (long)KVL_ * H_ * (DN_ + DV_));
    tohalf_kernel<<<(int)(((long)(H_ * DV_) * HIDDEN_ / 4 + 255) / 256), 256>>>(
        wo, woH, (long)(H_ * DV_) * HIDDEN_);

    // 1) q_a = hid @ wq_a           [2048 x 1536], K=5120 (float out)
    hgemm_kernel<0><<<dim3(QL_ / 128, 16), blk, GSMEM_BYTES>>>(
        hidH, wqa, qa32, T_, QL_, HIDDEN_, HIDDEN_, QL_, QL_);
    // 2) rmsnorm(q_a) -> half
    rmsnorm_h_kernel<<<T_, 256>>>(qa32, q_ln, qa16, QL_, QL_, QL_);
    // 3) q = q_a_n @ wq_b           [2048 x 6144], K=1536 (half out)
    hgemm_kernel<1><<<dim3(H_ * DQK_ / 128, 16), blk, GSMEM_BYTES>>>(
        qa16, wqb, q16, T_, H_ * DQK_, QL_, QL_, H_ * DQK_, H_ * DQK_);
    // 4) ckv = hid @ wkv_a          [2048 x 640], K=5120 (float out)
    hgemm_kernel<0><<<dim3(CKVP_ / 128, 16), blk, GSMEM_BYTES>>>(
        hidH, wkva, ckv, T_, CKVP_, HIDDEN_, HIDDEN_, CKVP_, CKVP_);
    // 5) cn = rmsnorm(ckv[:, :512]) -> half
    rmsnorm_h_kernel<<<T_, 256>>>(ckv, kv_ln, cn16, KVL_, CKVP_, KVL_);
    // 6) kv = cn @ wkv_b            [2048 x 8192], K=512 (half out)
    hgemm_kernel<1><<<dim3(H_ * (DN_ + DV_) / 128, 16), blk, GSMEM_BYTES>>>(
        cn16, wkvb, kv16, T_, H_ * (DN_ + DV_), KVL_,
        KVL_, H_ * (DN_ + DV_), H_ * (DN_ + DV_));
    // 7) RoPE on q_pe (half in place)
    rope_kernel<__half><<<dim3(H_, T_), 64>>>(q16 + DN_, q16 + DN_, cosT, sinT,
                                              H_ * DQK_, DQK_, H_ * DQK_, DQK_);
    // 8) RoPE on k_pe (float ckv) -> half kr
    rope_kernel<float><<<dim3(1, T_), 64>>>(ckv + KVL_, kr16, cosT, sinT,
                                            CKVP_, 0, DR_, 0);
    // 9) fused fp16 attention: ctx(half) = softmax(QK^T) @ V
    fused_attn_kernel<<<dim3(16, H_), blk, FUSED_SMEM>>>(q16, kv16, kr16, ctx16);
    // 10) out = ctx @ wo            [2048 x 5120], K=1024 (float out)
    hgemm_kernel<0><<<dim3(HIDDEN_ / 128, 16), blk, GSMEM_BYTES>>>(
        ctx16, woH, out, T_, HIDDEN_, H_ * DV_, H_ * DV_, HIDDEN_, HIDDEN_);
}

// round 9
// speedup vs baseline: 16.7324x; 1.1044x over previous
#include <cuda_runtime.h>
#include <cuda_fp16.h>
#include <math.h>

// ---------------------------------------------------------------------------
// DeepSeek V2 MLA attention prefill — fp16 mma.sync m16n8k16 + ldmatrix.
// GEMM1+GEMM4 merged (shared A, K=5120). Attention: full-tile K/V with
// phase-overlapped cp.async prefetch (V loads during S, next K during PV).
// ---------------------------------------------------------------------------

namespace {
constexpr int T_      = 2048;
constexpr int H_      = 32;
constexpr int HIDDEN_ = 5120;
constexpr int QL_     = 1536;
constexpr int KVL_    = 512;
constexpr int DN_     = 128;
constexpr int DR_     = 64;
constexpr int DQK_    = 192;
constexpr int DV_     = 128;
constexpr int CKVP_   = 640;                 // padded ckv width
constexpr int NMERGE_ = QL_ + CKVP_;         // 2176 (merged GEMM N)
constexpr float EPS_  = 1e-6f;
constexpr float SCALING_ = 0.07216878364870323f;  // 192^-0.5

// fp16 dense GEMM smem (halves)
constexpr int APAD_H = 40;
constexpr int BPAD_H = 136;
constexpr int ASTG_H = 128 * APAD_H;
constexpr int BSTG_H = 32 * BPAD_H;
constexpr int STG_H  = ASTG_H + BSTG_H;
constexpr int GSMEM_BYTES = 4 * STG_H * 2;

// fused attention smem (full tiles, halves + trailing floats)
constexpr int QPAD_B = 200;
constexpr int KPAD_B = 200;
constexpr int VPAD_B = 136;
constexpr int PPAD_B = 136;
constexpr int AQ_B   = 128 * QPAD_B;   // 25600
constexpr int AK_B   = 128 * KPAD_B;   // 25600
constexpr int AV_B   = 128 * VPAD_B;   // 17408
constexpr int AP_B   = 128 * PPAD_B;   // 17408
constexpr int AH_TOT = AQ_B + AK_B + AV_B + AP_B;   // 86016 halves
constexpr int FUSED_SMEM = AH_TOT * 2 + 640 * 4;    // 174592 B
}

// ------------------------- scratch (static device) -------------------------
__device__ __half g_hidH[(long)T_ * HIDDEN_];
__device__ float  g_qack[(long)T_ * NMERGE_];        // merged q_a | ckv
__device__ __half g_qa16[(long)T_ * QL_];
__device__ __half g_q16[(long)T_ * H_ * DQK_];
__device__ __half g_cn16[(long)T_ * KVL_];
__device__ __half g_kv16[(long)T_ * H_ * (DN_ + DV_)];
__device__ __half g_kr16[(long)T_ * DR_];
__device__ __half g_ctx16[(long)T_ * H_ * DV_];
// fp16 weights
__device__ __half g_wqac[(long)HIDDEN_ * NMERGE_];   // [wq_a | wkv_a(pad)]
__device__ __half g_wqb [(long)QL_ * (H_ * DQK_)];
__device__ __half g_wkvb[(long)KVL_ * (H_ * (DN_ + DV_))];
__device__ __half g_wo  [(long)(H_ * DV_) * HIDDEN_];

// ------------------------------ helpers ------------------------------------
__device__ __forceinline__ void mma_f16(float* d, const unsigned* a, const unsigned* b) {
    asm volatile(
        "mma.sync.aligned.m16n8k16.row.col.f32.f16.f16.f32 "
        "{%0,%1,%2,%3}, {%4,%5,%6,%7}, {%8,%9}, {%0,%1,%2,%3};"
        : "+f"(d[0]), "+f"(d[1]), "+f"(d[2]), "+f"(d[3])
        : "r"(a[0]), "r"(a[1]), "r"(a[2]), "r"(a[3]),
          "r"(b[0]), "r"(b[1]));
}

__device__ __forceinline__ void ldsm_x4(unsigned* r, unsigned addr) {
    asm volatile("ldmatrix.sync.aligned.m8n8.x4.shared.b16 {%0,%1,%2,%3}, [%4];"
                 : "=r"(r[0]), "=r"(r[1]), "=r"(r[2]), "=r"(r[3]) : "r"(addr));
}
__device__ __forceinline__ void ldsm_x4t(unsigned* r, unsigned addr) {
    asm volatile("ldmatrix.sync.aligned.m8n8.x4.trans.shared.b16 {%0,%1,%2,%3}, [%4];"
                 : "=r"(r[0]), "=r"(r[1]), "=r"(r[2]), "=r"(r[3]) : "r"(addr));
}

__device__ __forceinline__ unsigned smem_u32(const void* p) {
    return (unsigned)__cvta_generic_to_shared(p);
}
__device__ __forceinline__ void cp16(unsigned dst, const void* src) {
    asm volatile("cp.async.cg.shared.global [%0], [%1], 16;\n" :: "r"(dst), "l"(src));
}

// ------------------------------- FP16 GEMM ---------------------------------
// C[M,N] = A @ B. Tile 128x128x32, 4-stage cp.async. OUT: 0 float C, 1 half C.
template<int OUT>
__global__ __launch_bounds__(256, 2)
void hgemm_kernel(const __half* __restrict__ A,
                  const __half* __restrict__ B,
                  void* __restrict__ Cv,
                  int M, int N, int K,
                  int lda, int ldb, int ldc)
{
    constexpr int BK = 32, S = 4;
    const int bx = blockIdx.x, by = blockIdx.y;

    extern __shared__ __half hsm[];

    const int tid  = threadIdx.x;
    const int lane = tid & 31;
    const int warp = tid >> 5;
    const int gid  = lane >> 2;
    const int tig  = lane & 3;
    const int wr   = warp & 3;
    const int wc   = warp >> 2;
    const int rowBase = by * 128, colBase = bx * 128;
    const int wm = wr * 32, wn = wc * 64;

    const int tiles = K / BK;

    auto load_tile = [&](int st, int kt) {
        const int k0 = kt * BK;
        __half* As = hsm + st * STG_H;
        __half* Bs = As + ASTG_H;
        #pragma unroll
        for (int i = 0; i < 2; i++) {
            int c = tid + i * 256;
            int r = c >> 2, kc = (c & 3) * 8;
            cp16(smem_u32(As + r * APAD_H + kc),
                 A + (long)(rowBase + r) * lda + k0 + kc);
        }
        #pragma unroll
        for (int i = 0; i < 2; i++) {
            int c = tid + i * 256;
            int r = c >> 4, nc = (c & 15) * 8;
            cp16(smem_u32(Bs + r * BPAD_H + nc),
                 B + (long)(k0 + r) * ldb + colBase + nc);
        }
    };

    #pragma unroll
    for (int s = 0; s < S - 1; s++) {
        load_tile(s, s);
        asm volatile("cp.async.commit_group;\n");
    }

    float acc[2][8][4];
    #pragma unroll
    for (int i = 0; i < 2; i++)
        #pragma unroll
        for (int j = 0; j < 8; j++)
            #pragma unroll
            for (int v = 0; v < 4; v++) acc[i][j][v] = 0.0f;

    const int arow = lane & 15;
    const int acol = (lane >> 4) * 8;

    for (int t = 0; t < tiles; t++) {
        asm volatile("cp.async.wait_group %0;\n" :: "n"(S - 2));
        __syncthreads();

        int tn = t + S - 1;
        if (tn < tiles) load_tile(tn % S, tn);
        asm volatile("cp.async.commit_group;\n");

        const __half* Asb = hsm + (t % S) * STG_H;
        const __half* Bsb = Asb + ASTG_H;

        #pragma unroll
        for (int ks = 0; ks < 2; ks++) {
            const int kb = ks * 16;
            unsigned af[2][4];
            unsigned a0 = smem_u32(Asb + (wm + arow) * APAD_H + kb + acol);
            ldsm_x4(af[0], a0);
            ldsm_x4(af[1], a0 + 16 * APAD_H * 2);

            unsigned b0 = smem_u32(Bsb + (kb + arow) * BPAD_H + wn + acol);
            #pragma unroll
            for (int p = 0; p < 4; p++) {
                unsigned bf[4];
                ldsm_x4t(bf, b0 + p * 32);
                mma_f16(acc[0][2 * p    ], af[0], bf + 0);
                mma_f16(acc[0][2 * p + 1], af[0], bf + 2);
                mma_f16(acc[1][2 * p    ], af[1], bf + 0);
                mma_f16(acc[1][2 * p + 1], af[1], bf + 2);
            }
        }
    }

    #pragma unroll
    for (int mt = 0; mt < 2; mt++) {
        #pragma unroll
        for (int nt = 0; nt < 8; nt++) {
            int gc = colBase + wn + nt * 8 + tig * 2;
            #pragma unroll
            for (int half = 0; half < 2; half++) {
                int gr = rowBase + wm + mt * 16 + gid + half * 8;
                float x0 = acc[mt][nt][half * 2];
                float x1 = acc[mt][nt][half * 2 + 1];
                if (OUT == 0) {
                    float* C = (float*)Cv;
                    *reinterpret_cast<float2*>(&C[(long)gr * ldc + gc]) =
                        make_float2(x0, x1);
                } else {
                    __half* C = (__half*)Cv;
                    *reinterpret_cast<__half2*>(&C[(long)gr * ldc + gc]) =
                        __floats2half2_rn(x0, x1);
                }
            }
        }
    }
}

// --------------------- fused flash attention (fp16 mma) --------------------
// Full-tile K/V: V(j) prefetched during S-compute, K(j+1) during PV-compute.
__global__ __launch_bounds__(256, 1)
void fused_attn_kernel(const __half* __restrict__ q,
                       const __half* __restrict__ kv,
                       const __half* __restrict__ kr,
                       __half* __restrict__ ctx)
{
    extern __shared__ __half hs[];
    __half* Qs = hs;
    __half* Ks = hs + AQ_B;
    __half* Vs = hs + AQ_B + AK_B;
    __half* Ps = hs + AQ_B + AK_B + AV_B;
    float* fbase  = reinterpret_cast<float*>(hs + AH_TOT);
    float* row_m  = fbase;
    float* row_l  = fbase + 128;
    float* row_r  = fbase + 256;
    float* rowred = fbase + 384;

    const int qt = 15 - blockIdx.x;
    const int h  = blockIdx.y;
    const long q0 = (long)qt * 128;

    const int tid  = threadIdx.x;
    const int lane = tid & 31;
    const int warp = tid >> 5;
    const int gid  = lane >> 2;
    const int tig  = lane & 3;
    const int wr   = warp & 3;
    const int wc   = warp >> 2;
    const int wm = wr * 32, wn = wc * 64;
    const int KVROW = H_ * (DN_ + DV_);

    const int arow = lane & 15;
    const int acol = (lane >> 4) * 8;
    const int krow_off = ((lane >> 4) << 3) + (lane & 7);
    const int kcol_off = ((lane >> 3) & 1) << 3;

    if (tid < 128) { row_m[tid] = -1e30f; row_l[tid] = 0.0f; }

    // K tile loader: 128 keys x 192 d (nope cols 0-127 from kv, rope from kr)
    auto load_K = [&](int j) {
        const long key0 = (long)j * 128;
        #pragma unroll
        for (int i = 0; i < 12; i++) {
            int e = tid + i * 256;           // 0..3071
            int r = e / 24;
            int fc = (e % 24) * 8;
            const __half* src = (fc < DN_)
                ? kv + (key0 + r) * (long)KVROW + h * (DN_ + DV_) + fc
                : kr + (key0 + r) * (long)DR_ + (fc - DN_);
            cp16(smem_u32(Ks + r * KPAD_B + fc), src);
        }
    };
    // V tile loader: 128 keys x 128 dv
    auto load_V = [&](int j) {
        const long key0 = (long)j * 128;
        #pragma unroll
        for (int i = 0; i < 8; i++) {
            int e = tid + i * 256;           // 0..2047
            int r = e >> 4;
            int fc = (e & 15) * 8;
            cp16(smem_u32(Vs + r * VPAD_B + fc),
                 kv + (key0 + r) * (long)KVROW + h * (DN_ + DV_) + DN_ + fc);
        }
    };

    // prologue: Q tile + K(0), one commit group
    const __half* Qbase = q + q0 * (H_ * DQK_) + h * DQK_;
    #pragma unroll
    for (int i = 0; i < 12; i++) {
        int e = tid + i * 256;
        int r = e / 24;
        int fc = (e % 24) * 8;
        cp16(smem_u32(Qs + r * QPAD_B + fc), Qbase + (long)r * (H_ * DQK_) + fc);
    }
    load_K(0);
    asm volatile("cp.async.commit_group;\n");

    float Oacc[2][8][4];
    #pragma unroll
    for (int i = 0; i < 2; i++)
        #pragma unroll
        for (int j = 0; j < 8; j++)
            #pragma unroll
            for (int v = 0; v < 4; v++) Oacc[i][j][v] = 0.0f;

    for (int j = 0; j <= qt; j++) {
        const bool diag = (j == qt);

        // issue V(j); wait for Q+K(j) (previous group)
        load_V(j);
        asm volatile("cp.async.commit_group;\n");
        asm volatile("cp.async.wait_group 1;\n");
        __syncthreads();

        // ---- S = Q @ K^T over full tile (6 x 32d, no intra-syncs)
        float Sacc[2][8][4];
        #pragma unroll
        for (int i = 0; i < 2; i++)
            #pragma unroll
            for (int jj = 0; jj < 8; jj++)
                #pragma unroll
                for (int v = 0; v < 4; v++) Sacc[i][jj][v] = 0.0f;

        #pragma unroll
        for (int c = 0; c < 6; c++) {
            const int dbase = c * 32;
            #pragma unroll
            for (int ks = 0; ks < 2; ks++) {
                const int kb = dbase + ks * 16;
                unsigned af[2][4];
                unsigned a0 = smem_u32(Qs + (wm + arow) * QPAD_B + kb + acol);
                ldsm_x4(af[0], a0);
                ldsm_x4(af[1], a0 + 16 * QPAD_B * 2);
                #pragma unroll
                for (int nt2 = 0; nt2 < 4; nt2++) {
                    unsigned bf[4];
                    unsigned b0 = smem_u32(Ks + (wn + nt2 * 16 + krow_off) * KPAD_B
                                           + kb + kcol_off);
                    ldsm_x4(bf, b0);
                    mma_f16(Sacc[0][2 * nt2    ], af[0], bf + 0);
                    mma_f16(Sacc[0][2 * nt2 + 1], af[0], bf + 2);
                    mma_f16(Sacc[1][2 * nt2    ], af[1], bf + 0);
                    mma_f16(Sacc[1][2 * nt2 + 1], af[1], bf + 2);
                }
            }
        }

        // ---- scale + causal mask
        #pragma unroll
        for (int mt = 0; mt < 2; mt++)
            #pragma unroll
            for (int nt = 0; nt < 8; nt++)
                #pragma unroll
                for (int v = 0; v < 4; v++) {
                    int rl = wm + mt * 16 + (v >> 1) * 8 + gid;
                    int cl = wn + nt * 8 + tig * 2 + (v & 1);
                    float s = Sacc[mt][nt][v] * SCALING_;
                    if (diag && cl > rl) s = -1e30f;
                    Sacc[mt][nt][v] = s;
                }

        // ---- row max
        #pragma unroll
        for (int mt = 0; mt < 2; mt++)
            #pragma unroll
            for (int half = 0; half < 2; half++) {
                int ri = wm + mt * 16 + half * 8 + gid;
                float mx = -1e30f;
                #pragma unroll
                for (int nt = 0; nt < 8; nt++) {
                    mx = fmaxf(mx, Sacc[mt][nt][half * 2]);
                    mx = fmaxf(mx, Sacc[mt][nt][half * 2 + 1]);
                }
                mx = fmaxf(mx, __shfl_xor_sync(0xffffffffu, mx, 1));
                mx = fmaxf(mx, __shfl_xor_sync(0xffffffffu, mx, 2));
                if (tig == 0) rowred[wc * 128 + ri] = mx;
            }
        __syncthreads();
        if (tid < 128) {
            float tm = fmaxf(rowred[tid], rowred[128 + tid]);
            float mo = row_m[tid];
            float mn = fmaxf(mo, tm);
            row_m[tid] = mn;
            row_r[tid] = __expf(mo - mn);
        }
        __syncthreads();

        // ---- exp, P (half) write, row sum, O rescale
        #pragma unroll
        for (int mt = 0; mt < 2; mt++)
            #pragma unroll
            for (int half = 0; half < 2; half++) {
                int ri = wm + mt * 16 + half * 8 + gid;
                float m = row_m[ri];
                float rsc = row_r[ri];
                float s = 0.0f;
                #pragma unroll
                for (int nt = 0; nt < 8; nt++) {
                    float p0 = __expf(Sacc[mt][nt][half * 2    ] - m);
                    float p1 = __expf(Sacc[mt][nt][half * 2 + 1] - m);
                    __half2 hv = __floats2half2_rn(p0, p1);
                    int cl = wn + nt * 8 + tig * 2;
                    *reinterpret_cast<__half2*>(&Ps[ri * PPAD_B + cl]) = hv;
                    float2 pr = __half22float2(hv);
                    s += pr.x + pr.y;
                    Oacc[mt][nt][half * 2    ] *= rsc;
                    Oacc[mt][nt][half * 2 + 1] *= rsc;
                }
                s += __shfl_xor_sync(0xffffffffu, s, 1);
                s += __shfl_xor_sync(0xffffffffu, s, 2);
                if (tig == 0) rowred[wc * 128 + ri] = s;
            }
        __syncthreads();
        if (tid < 128)
            row_l[tid] = row_l[tid] * row_r[tid] + rowred[tid] + rowred[128 + tid];

        // issue K(j+1) (safe: all S reads of Ks done before the syncs above);
        // then wait for V(j)
        if (j < qt) {
            load_K(j + 1);
            asm volatile("cp.async.commit_group;\n");
            asm volatile("cp.async.wait_group 1;\n");
        } else {
            asm volatile("cp.async.wait_group 0;\n");
        }
        __syncthreads();

        // ---- O += P @ V over full tile (4 x 32k, no intra-syncs)
        #pragma unroll
        for (int c = 0; c < 4; c++) {
            #pragma unroll
            for (int ks = 0; ks < 2; ks++) {
                const int kc = c * 32 + ks * 16;
                unsigned af[2][4];
                unsigned a0 = smem_u32(Ps + (wm + arow) * PPAD_B + kc + acol);
                ldsm_x4(af[0], a0);
                ldsm_x4(af[1], a0 + 16 * PPAD_B * 2);
                unsigned vb = smem_u32(Vs + (kc + arow) * VPAD_B + wn + acol);
                #pragma unroll
                for (int p = 0; p < 4; p++) {
                    unsigned bf[4];
                    ldsm_x4t(bf, vb + p * 32);
                    mma_f16(Oacc[0][2 * p    ], af[0], bf + 0);
                    mma_f16(Oacc[0][2 * p + 1], af[0], bf + 2);
                    mma_f16(Oacc[1][2 * p    ], af[1], bf + 0);
                    mma_f16(Oacc[1][2 * p + 1], af[1], bf + 2);
                }
            }
        }
        __syncthreads();   // Vs/Ps reads done before next j overwrites
    }

    // ---- epilogue: O /= l, write half ctx
    #pragma unroll
    for (int mt = 0; mt < 2; mt++)
        #pragma unroll
        for (int half = 0; half < 2; half++) {
            int ri = wm + mt * 16 + half * 8 + gid;
            float inv = 1.0f / row_l[ri];
            long t = q0 + ri;
            #pragma unroll
            for (int nt = 0; nt < 8; nt++) {
                int cl = wn + nt * 8 + tig * 2;
                __half2 hv = __floats2half2_rn(Oacc[mt][nt][half * 2] * inv,
                                               Oacc[mt][nt][half * 2 + 1] * inv);
                *reinterpret_cast<__half2*>(&ctx[t * (H_ * DV_) + h * DV_ + cl]) = hv;
            }
        }
}

// ------------------------------ prep kernels --------------------------------
__global__ void tohalf_kernel(const float* __restrict__ in,
                              __half* __restrict__ out, long n)
{
    long i = ((long)blockIdx.x * blockDim.x + threadIdx.x) * 4;
    if (i < n) {
        float4 v = *reinterpret_cast<const float4*>(in + i);
        union { __half2 h[2]; uint2 u; } cv;
        cv.h[0] = __floats2half2_rn(v.x, v.y);
        cv.h[1] = __floats2half2_rn(v.z, v.w);
        *reinterpret_cast<uint2*>(out + i) = cv.u;
    }
}

// strided fp32->fp16 copy, 8 halves/thread, zero-pad beyond Cin.
// grid covers exactly R * chunks threads (chunks = dest width / 8).
__global__ void tohalf8_strided(const float* __restrict__ in, int ldin, int Cin,
                                __half* __restrict__ out, int ldout, int chunks)
{
    long idx = (long)blockIdx.x * blockDim.x + threadIdx.x;
    int r  = (int)(idx / chunks);
    int c  = (int)(idx % chunks) * 8;
    union { __half2 h[4]; uint4 u; } cv;
    if (c < Cin) {
        const float* src = in + (long)r * ldin + c;
        float4 a = *reinterpret_cast<const float4*>(src);
        float4 b = *reinterpret_cast<const float4*>(src + 4);
        cv.h[0] = __floats2half2_rn(a.x, a.y);
        cv.h[1] = __floats2half2_rn(a.z, a.w);
        cv.h[2] = __floats2half2_rn(b.x, b.y);
        cv.h[3] = __floats2half2_rn(b.z, b.w);
    } else {
        cv.u = make_uint4(0, 0, 0, 0);
    }
    *reinterpret_cast<uint4*>(out + (long)r * ldout + c) = cv.u;
}

// ------------------------------ RMSNorm (half out) --------------------------
__global__ void rmsnorm_h_kernel(const float* __restrict__ x,
                                 const float* __restrict__ w,
                                 __half* __restrict__ y,
                                 int L, int ldx, int ldy)
{
    const int row = blockIdx.x, tid = threadIdx.x;
    const float* xr = x + (long)row * ldx;
    __half* yr = y + (long)row * ldy;

    __shared__ float red[256];
    float s = 0.0f;
    for (int i = tid; i < L; i += 256) { float v = xr[i]; s += v * v; }
    red[tid] = s; __syncthreads();
    for (int o = 128; o > 0; o >>= 1) {
        if (tid < o) red[tid] += red[tid + o];
        __syncthreads();
    }
    const float scale = rsqrtf(red[0] / (float)L + EPS_);
    for (int i = tid; i < L; i += 256)
        yr[i] = __float2half_rn(xr[i] * scale * w[i]);
}

// -------------------------------- RoPE (half out) ---------------------------
template<typename Tin>
__global__ void rope_kernel(const Tin* __restrict__ x, __half* __restrict__ o,
                            const float* __restrict__ cosT,
                            const float* __restrict__ sinT,
                            long sxt, int sxh, long sot, int soh)
{
    const int h = blockIdx.x, t = blockIdx.y, i = threadIdx.x;  // i < 64
    const Tin* xp = x + (long)t * sxt + (long)h * sxh;
    __half* op = o + (long)t * sot + (long)h * soh;

    __shared__ float xs[64];
    __shared__ float ys[64];
    xs[i] = (float)xp[i];
    __syncthreads();
    float y = (i < 32) ? xs[2 * i] : xs[2 * (i - 32) + 1];
    ys[i] = y;
    __syncthreads();
    float rot = (i < 32) ? -ys[i + 32] : ys[i - 32];
    op[i] = __float2half_rn(y * cosT[(long)t * DR_ + i]
                            + rot * sinT[(long)t * DR_ + i]);
}

// ------------------------------- launch ------------------------------------
extern "C" void kernel_launch(void* const* d_in, const int* in_sizes, int n_in,
                              void* d_out, int out_size)
{
    const float* hidden = (const float*)d_in[0];
    const float* cosT   = (const float*)d_in[1];
    const float* sinT   = (const float*)d_in[2];
    const float* wq_a   = (const float*)d_in[3];
    const float* q_ln   = (const float*)d_in[4];
    const float* wq_b   = (const float*)d_in[5];
    const float* wkv_a  = (const float*)d_in[6];
    const float* kv_ln  = (const float*)d_in[7];
    const float* wkv_b  = (const float*)d_in[8];
    const float* wo     = (const float*)d_in[9];
    float* out = (float*)d_out;

    static __half *hidH = nullptr, *qa16 = nullptr, *q16 = nullptr,
                  *cn16 = nullptr, *kv16 = nullptr, *kr16 = nullptr,
                  *ctx16 = nullptr, *wqac = nullptr, *wqb = nullptr,
                  *wkvb = nullptr, *woH = nullptr;
    static float *qack = nullptr;
    if (!qack) {
        cudaGetSymbolAddress((void**)&hidH,  g_hidH);
        cudaGetSymbolAddress((void**)&qack,  g_qack);
        cudaGetSymbolAddress((void**)&qa16,  g_qa16);
        cudaGetSymbolAddress((void**)&q16,   g_q16);
        cudaGetSymbolAddress((void**)&cn16,  g_cn16);
        cudaGetSymbolAddress((void**)&kv16,  g_kv16);
        cudaGetSymbolAddress((void**)&kr16,  g_kr16);
        cudaGetSymbolAddress((void**)&ctx16, g_ctx16);
        cudaGetSymbolAddress((void**)&wqac,  g_wqac);
        cudaGetSymbolAddress((void**)&wqb,   g_wqb);
        cudaGetSymbolAddress((void**)&wkvb,  g_wkvb);
        cudaGetSymbolAddress((void**)&woH,   g_wo);
        cudaFuncSetAttribute(hgemm_kernel<0>,
                             cudaFuncAttributeMaxDynamicSharedMemorySize, GSMEM_BYTES);
        cudaFuncSetAttribute(hgemm_kernel<1>,
                             cudaFuncAttributeMaxDynamicSharedMemorySize, GSMEM_BYTES);
        cudaFuncSetAttribute(fused_attn_kernel,
                             cudaFuncAttributeMaxDynamicSharedMemorySize, FUSED_SMEM);
    }

    const dim3 blk(256);

    // 0) prep: fp16 hidden; weights -> fp16 (wq_a|wkv_a merged into wqac)
    tohalf_kernel<<<(int)(((long)T_ * HIDDEN_ / 4 + 255) / 256), 256>>>(
        hidden, hidH, (long)T_ * HIDDEN_);
    tohalf8_strided<<<(HIDDEN_ * (QL_ / 8)) / 256, 256>>>(
        wq_a, QL_, QL_, wqac, NMERGE_, QL_ / 8);
    tohalf8_strided<<<(HIDDEN_ * (CKVP_ / 8)) / 256, 256>>>(
        wkv_a, KVL_ + DR_, KVL_ + DR_, wqac + QL_, NMERGE_, CKVP_ / 8);
    tohalf_kernel<<<(int)(((long)QL_ * H_ * DQK_ / 4 + 255) / 256), 256>>>(
        wq_b, wqb, (long)QL_ * H_ * DQK_);
    tohalf_kernel<<<(int)(((long)KVL_ * H_ * (DN_ + DV_) / 4 + 255) / 256), 256>>>(
        wkv_b, wkvb, (long)KVL_ * H_ * (DN_ + DV_));
    tohalf_kernel<<<(int)(((long)(H_ * DV_) * HIDDEN_ / 4 + 255) / 256), 256>>>(
        wo, woH, (long)(H_ * DV_) * HIDDEN_);

    // 1) [q_a | ckv] = hid @ [wq_a | wkv_a]   [2048 x 2176], K=5120 (float)
    hgemm_kernel<0><<<dim3(NMERGE_ / 128, 16), blk, GSMEM_BYTES>>>(
        hidH, wqac, qack, T_, NMERGE_, HIDDEN_, HIDDEN_, NMERGE_, NMERGE_);
    // 2) rmsnorm(q_a) -> half
    rmsnorm_h_kernel<<<T_, 256>>>(qack, q_ln, qa16, QL_, NMERGE_, QL_);
    // 3) q = q_a_n @ wq_b           [2048 x 6144], K=1536 (half out)
    hgemm_kernel<1><<<dim3(H_ * DQK_ / 128, 16), blk, GSMEM_BYTES>>>(
        qa16, wqb, q16, T_, H_ * DQK_, QL_, QL_, H_ * DQK_, H_ * DQK_);
    // 5) cn = rmsnorm(ckv[:, :512]) -> half
    rmsnorm_h_kernel<<<T_, 256>>>(qack + QL_, kv_ln, cn16, KVL_, NMERGE_, KVL_);
    // 6) kv = cn @ wkv_b            [2048 x 8192], K=512 (half out)
    hgemm_kernel<1><<<dim3(H_ * (DN_ + DV_) / 128, 16), blk, GSMEM_BYTES>>>(
        cn16, wkvb, kv16, T_, H_ * (DN_ + DV_), KVL_,
        KVL_, H_ * (DN_ + DV_), H_ * (DN_ + DV_));
    // 7) RoPE on q_pe (half in place)
    rope_kernel<__half><<<dim3(H_, T_), 64>>>(q16 + DN_, q16 + DN_, cosT, sinT,
                                              H_ * DQK_, DQK_, H_ * DQK_, DQK_);
    // 8) RoPE on k_pe (float, merged buffer col 2048) -> half kr
    rope_kernel<float><<<dim3(1, T_), 64>>>(qack + QL_ + KVL_, kr16, cosT, sinT,
                                            NMERGE_, 0, DR_, 0);
    // 9) fused fp16 attention: ctx(half) = softmax(QK^T) @ V
    fused_attn_kernel<<<dim3(16, H_), blk, FUSED_SMEM>>>(q16, kv16, kr16, ctx16);
    // 10) out = ctx @ wo            [2048 x 5120], K=1024 (float out)
    hgemm_kernel<0><<<dim3(HIDDEN_ / 128, 16), blk, GSMEM_BYTES>>>(
        ctx16, woH, out, T_, HIDDEN_, H_ * DV_, H_ * DV_, HIDDEN_, HIDDEN_);
}